// round 13
// baseline (speedup 1.0000x reference)
#include <cuda_runtime.h>
#include <cuda_fp16.h>
#include <math.h>
#include <cstdint>

#define NN 10000
#define EE 160000
#define CC 32
#define NB 128
#define HH 64
#define FD 512   // C * (1+3+5+7)

typedef unsigned long long u64t;
typedef ulonglong2 u642;

// ---------------- scratch (device globals; no allocation) ----------------
__device__ u64t   g_hp[(size_t)EE*32];     // 41 MB  : hidden, packed m-pair layout [b][k][mp]
__device__ float  g_sh[(size_t)EE*16];     // 10 MB  : sph harmonics, edge order
__device__ float  g_sh2[(size_t)EE*16];    // 10 MB  : sph harmonics, CSR order
__device__ __half g_wall2[(size_t)EE*384]; // 123 MB : layer weights, edge order, fp16
__device__ __half g_ew2[(size_t)EE*128];   // 41 MB  : edge-out weights, edge order, fp16
__device__ float  g_fa[(size_t)NN*FD];     // 20 MB  : node features buf A
__device__ float  g_fb[(size_t)NN*FD];     // 20 MB  : node features buf B
__device__ float  g_f0a[(size_t)NN*CC];    // 1.28 MB: compact f0 buf A
__device__ float  g_f0b[(size_t)NN*CC];    // 1.28 MB: compact f0 buf B
__device__ int    g_cnt[NN];
__device__ int    g_cnt2[NN];
__device__ int    g_off[NN+1];
__device__ int    g_eid[EE];               // CSR position -> edge
__device__ int    g_src[EE];               // CSR position -> src node

// ---------------- packed fp32 helpers ----------------
__device__ __forceinline__ u64t pack2(float v) {
    u64t r; asm("mov.b64 %0, {%1, %1};" : "=l"(r) : "f"(v)); return r;
}
__device__ __forceinline__ u64t pack2two(float lo, float hi) {
    u64t r; asm("mov.b64 %0, {%1, %2};" : "=l"(r) : "f"(lo), "f"(hi)); return r;
}
__device__ __forceinline__ void unpack2(u64t v, float& lo, float& hi) {
    asm("mov.b64 {%0, %1}, %2;" : "=f"(lo), "=f"(hi) : "l"(v));
}
__device__ __forceinline__ void ffma2(u64t& d, u64t a, u64t b) {
    asm("fma.rn.f32x2 %0, %1, %2, %0;" : "+l"(d) : "l"(a), "l"(b));
}

// ---------------- CSR build ----------------
__global__ void k_zero() {
    int i = blockIdx.x*blockDim.x + threadIdx.x;
    if (i < NN) { g_cnt[i] = 0; g_cnt2[i] = 0; }
}

__global__ void k_hist(const int* __restrict__ ei) {
    int e = blockIdx.x*blockDim.x + threadIdx.x;
    if (e < EE) atomicAdd(&g_cnt[ei[EE + e]], 1);
}

// one-pass parallel scan: 1024 threads, 10 contiguous elems each (NN = 1000*10)
__global__ void k_scan() {
    __shared__ int wsum[32];
    int t = threadIdx.x;
    int lane = t & 31, wid = t >> 5;
    int base = t*10;
    int loc[10];
    int s = 0;
    if (t < 1000) {
        #pragma unroll
        for (int j = 0; j < 10; j++) { s += g_cnt[base + j]; loc[j] = s; }
    }
    int v = s;
    #pragma unroll
    for (int o = 1; o < 32; o <<= 1) {
        int u = __shfl_up_sync(0xFFFFFFFF, v, o);
        if (lane >= o) v += u;
    }
    if (lane == 31) wsum[wid] = v;
    __syncthreads();
    if (wid == 0) {
        int w = wsum[lane];
        #pragma unroll
        for (int o = 1; o < 32; o <<= 1) {
            int u = __shfl_up_sync(0xFFFFFFFF, w, o);
            if (lane >= o) w += u;
        }
        wsum[lane] = w;
    }
    __syncthreads();
    int excl = v - s + (wid > 0 ? wsum[wid-1] : 0);
    if (t < 1000) {
        #pragma unroll
        for (int j = 0; j < 10; j++) g_off[base + j + 1] = excl + loc[j];
    }
    if (t == 0) g_off[0] = 0;
}

// fill: eid/src permutation + CSR-ordered copy of sh
__global__ void k_fill(const int* __restrict__ ei) {
    int e = blockIdx.x*blockDim.x + threadIdx.x;
    if (e < EE) {
        int d = ei[EE + e];
        int p = atomicAdd(&g_cnt2[d], 1);
        int slot = g_off[d] + p;
        g_eid[slot] = e;
        g_src[slot] = ei[e];
        const float4* src = (const float4*)&g_sh[(size_t)e*16];
        float4* dst = (float4*)&g_sh2[(size_t)slot*16];
        dst[0] = src[0]; dst[1] = src[1]; dst[2] = src[2]; dst[3] = src[3];
    }
}

// ---------------- fused: geometry + sh + radial basis + MLP1 (f32x2, 128 edges/block) ----
// output: g_hp in packed m-pair layout (k-major) for zero-transpose GEMM staging
#define GEOMH_SMEM 99328
__global__ void k_geomh(const float* __restrict__ pos, const float* __restrict__ rw1,
                        const float* __restrict__ rb1, const int* __restrict__ ei) {
    extern __shared__ char smem[];
    float* rb_s = (float*)smem;
    float* b1_s = (float*)(smem + 65536);
    float* su   = (float*)(smem + 98304);
    float* ss   = (float*)(smem + 98816);
    int tid = threadIdx.x;
    int eb = blockIdx.x*128;

    if (tid < 128) {
        int e = eb + tid;
        int sn = ei[e], dn = ei[EE + e];
        float vx = pos[dn*3+0] - pos[sn*3+0];
        float vy = pos[dn*3+1] - pos[sn*3+1];
        float vz = pos[dn*3+2] - pos[sn*3+2];
        float r2 = vx*vx + vy*vy + vz*vz + 1e-12f;
        float r  = sqrtf(r2);
        float inv_r = 1.0f / r;
        float x = vx*inv_r, y = vy*inv_r, z = vz*inv_r;

        const float s3  = 1.7320508075688772f;
        const float s15 = 3.872983346207417f;
        const float s5h = 1.118033988749895f;
        const float s15h= 1.9364916731037085f;
        const float c1  = 2.091650066335189f;
        const float c2  = 10.246950765959598f;
        const float c3  = 1.6201851746019651f;
        const float c4  = 1.3228756555322954f;
        const float c5  = 5.123475382979799f;
        float4 q0 = make_float4(1.0f, s3*x, s3*y, s3*z);
        float4 q1 = make_float4(s15*x*y, s15*y*z, s5h*(3.0f*z*z - 1.0f), s15*x*z);
        float4 q2 = make_float4(s15h*(x*x - y*y), c1*y*(3.0f*x*x - y*y), c2*x*y*z,
                                c3*y*(5.0f*z*z - 1.0f));
        float4 q3 = make_float4(c4*(5.0f*z*z*z - 3.0f*z), c3*x*(5.0f*z*z - 1.0f),
                                c5*z*(x*x - y*y), c1*x*(x*x - 3.0f*y*y));
        float4* shp = (float4*)&g_sh[(size_t)e*16];
        shp[0] = q0; shp[1] = q1; shp[2] = q2; shp[3] = q3;

        float u = fminf(r * 0.2f, 1.0f);
        float env = 0.5f * (cospif(u) + 1.0f);
        su[tid] = u;
        ss[tid] = env * 0.6324555320336759f * inv_r;
    }
    {
        const float4* src = (const float4*)rw1;
        float4* dst = (float4*)b1_s;
        #pragma unroll
        for (int i = tid; i < 2048; i += 256) dst[i] = src[i];
    }
    __syncthreads();

    {
        int e = tid & 127, kh = tid >> 7;
        float u = su[e], sc = ss[e];
        #pragma unroll 4
        for (int j = 0; j < 64; j++) {
            int k = kh*64 + j;
            rb_s[k*128 + e] = sc * sinpif((float)(k+1) * u);
        }
    }
    __syncthreads();

    int ty = tid >> 4, tx = tid & 15;
    u64t acc[4][4];
    #pragma unroll
    for (int p = 0; p < 4; p++)
        #pragma unroll
        for (int c = 0; c < 4; c++) acc[p][c] = 0ull;

    #pragma unroll 4
    for (int k = 0; k < 128; k++) {
        u64t ap[4];
        #pragma unroll
        for (int p = 0; p < 4; p++)
            ap[p] = *(const u64t*)&rb_s[k*128 + ty*8 + 2*p];
        float4 bv = *(const float4*)&b1_s[k*64 + tx*4];
        u64t bp[4] = {pack2(bv.x), pack2(bv.y), pack2(bv.z), pack2(bv.w)};
        #pragma unroll
        for (int p = 0; p < 4; p++)
            #pragma unroll
            for (int c = 0; c < 4; c++)
                ffma2(acc[p][c], ap[p], bp[c]);
    }

    // silu + bias, keep in registers
    float4 bias = *(const float4*)&rb1[tx*4];
    float bb[4] = {bias.x, bias.y, bias.z, bias.w};
    float lov[4][4], hiv[4][4];
    #pragma unroll
    for (int p = 0; p < 4; p++) {
        #pragma unroll
        for (int c = 0; c < 4; c++) {
            float lo, hi;
            unpack2(acc[p][c], lo, hi);
            float a = lo + bb[c];
            float b = hi + bb[c];
            lov[p][c] = a / (1.0f + expf(-a));
            hiv[p][c] = b / (1.0f + expf(-b));
        }
    }

    // transpose bounce through smem (rb_s dead) into packed m-pair layout, stride 66
    __syncthreads();
    {
        u64t* pk = (u64t*)smem;
        #pragma unroll
        for (int p = 0; p < 4; p++) {
            int mp = ty*4 + p;
            #pragma unroll
            for (int c = 0; c < 4; c++) {
                int k = tx*4 + c;
                pk[k*66 + mp] = pack2two(lov[p][c], hiv[p][c]);
            }
        }
    }
    __syncthreads();
    {
        const u64t* pk = (const u64t*)smem;
        u642* dst = (u642*)&g_hp[(size_t)blockIdx.x*4096];
        #pragma unroll
        for (int q = 0; q < 8; q++) {
            int li = tid + q*256;
            int k = li >> 5, mq = li & 31;
            dst[li] = *(const u642*)&pk[k*66 + mq*2];
        }
    }
}

// ---------------- GEMM2 (f32x2, fp16 out; zero-transpose A staging; LDS.128 A) ----
#define AST 66
#define BST 132
#define GEMM_SMEM (64*AST*8 + 64*BST*4)   // 33792 + 33792 = 67584
__global__ void k_gemm(const float* __restrict__ rw2, const float* __restrict__ edge_w,
                       const float* __restrict__ rb2, const float* __restrict__ edge_b) {
    extern __shared__ char smg[];
    u64t*  As2 = (u64t*)smg;
    float* Bs  = (float*)(smg + 64*AST*8);
    int tid = threadIdx.x;
    int bx = blockIdx.x, by = blockIdx.y;
    int eb = bx*128;

    // stage A: pure coalesced copy, no transpose
    {
        const u642* src = (const u642*)&g_hp[(size_t)bx*4096];
        #pragma unroll
        for (int q = 0; q < 8; q++) {
            int li = tid + q*256;
            int k = li >> 5, mq = li & 31;
            *(u642*)&As2[k*AST + mq*2] = src[li];
        }
    }
    #pragma unroll
    for (int p = 0; p < 8; p++) {
        int li = tid + p*256;
        int k = li >> 5, n4 = li & 31;
        int jg = by*128 + n4*4;
        float4 v = (jg < 384) ? *(const float4*)&rw2[k*384 + jg]
                              : *(const float4*)&edge_w[k*128 + (jg - 384)];
        *(float4*)&Bs[k*BST + n4*4] = v;
    }
    __syncthreads();

    int my = tid >> 4, nx = tid & 15;
    u64t acc[4][8];
    #pragma unroll
    for (int i = 0; i < 4; i++)
        #pragma unroll
        for (int n = 0; n < 8; n++) acc[i][n] = 0ull;

    #pragma unroll 8
    for (int k = 0; k < 64; k++) {
        u642 A0 = *(const u642*)&As2[k*AST + my*4];
        u642 A1 = *(const u642*)&As2[k*AST + my*4 + 2];
        u64t a[4] = {A0.x, A0.y, A1.x, A1.y};
        float4 b0 = *(const float4*)&Bs[k*BST + nx*8];
        float4 b1 = *(const float4*)&Bs[k*BST + nx*8 + 4];
        u64t bp[8] = {pack2(b0.x), pack2(b0.y), pack2(b0.z), pack2(b0.w),
                      pack2(b1.x), pack2(b1.y), pack2(b1.z), pack2(b1.w)};
        #pragma unroll
        for (int i = 0; i < 4; i++)
            #pragma unroll
            for (int n = 0; n < 8; n++)
                ffma2(acc[i][n], a[i], bp[n]);
    }

    float bj[8];
    #pragma unroll
    for (int n = 0; n < 8; n++) {
        int jg = by*128 + nx*8 + n;
        bj[n] = (jg < 384) ? rb2[jg] : edge_b[jg - 384];
    }

    #pragma unroll
    for (int i = 0; i < 4; i++) {
        float lo[8], hi[8];
        #pragma unroll
        for (int n = 0; n < 8; n++) {
            unpack2(acc[i][n], lo[n], hi[n]);
            lo[n] += bj[n]; hi[n] += bj[n];
        }
        int er0 = eb + my*8 + 2*i;
        __half* dst;
        size_t r0, r1;
        if (by < 3) {
            dst = g_wall2;
            r0 = (size_t)er0*384       + by*128 + nx*8;
            r1 = (size_t)(er0 + 1)*384 + by*128 + nx*8;
        } else {
            dst = g_ew2;
            r0 = (size_t)er0*128       + nx*8;
            r1 = (size_t)(er0 + 1)*128 + nx*8;
        }
        __half2 a0 = __floats2half2_rn(lo[0], lo[1]);
        __half2 a1 = __floats2half2_rn(lo[2], lo[3]);
        __half2 a2 = __floats2half2_rn(lo[4], lo[5]);
        __half2 a3 = __floats2half2_rn(lo[6], lo[7]);
        uint4 u0;
        u0.x = *(unsigned*)&a0; u0.y = *(unsigned*)&a1;
        u0.z = *(unsigned*)&a2; u0.w = *(unsigned*)&a3;
        *(uint4*)&dst[r0] = u0;
        __half2 c0 = __floats2half2_rn(hi[0], hi[1]);
        __half2 c1 = __floats2half2_rn(hi[2], hi[3]);
        __half2 c2 = __floats2half2_rn(hi[4], hi[5]);
        __half2 c3 = __floats2half2_rn(hi[6], hi[7]);
        uint4 u1;
        u1.x = *(unsigned*)&c0; u1.y = *(unsigned*)&c1;
        u1.z = *(unsigned*)&c2; u1.w = *(unsigned*)&c3;
        *(uint4*)&dst[r1] = u1;
    }
}

// ---------------- node feature init (compact f0 only) ----------------
__global__ void k_init(const float* __restrict__ node_embed, const int* __restrict__ species) {
    int i = blockIdx.x*blockDim.x + threadIdx.x;
    if (i < NN*CC) {
        int n = i >> 5, idx = i & 31;
        g_f0a[i] = node_embed[species[n]*32 + idx];
    }
}

// ---------------- one message-passing layer (round-8 structure, 128 threads) ----------
template<int LVAL>
__device__ __forceinline__ void layer_warp(int t, int lane, int e0, int e1, bool uself,
                                           const float* __restrict__ f0p,
                                           const float* __restrict__ sw,
                                           const float* __restrict__ mw,
                                           const float* s_f, float* s_agg, float* s_new) {
    constexpr int dim = 2*LVAL + 1;
    constexpr int off = 32*LVAL*LVAL;
    constexpr int shoff = LVAL*LVAL;
    const int wcol = t*128 + LVAL*32 + lane;

    float acc[dim];
    #pragma unroll
    for (int m = 0; m < dim; m++) acc[m] = 0.f;

    int ii = e0;
    #pragma unroll 1
    for (; ii + 4 <= e1; ii += 4) {
        int ea = g_eid[ii],   ebx = g_eid[ii+1];
        int ec = g_eid[ii+2], edx = g_eid[ii+3];
        float wa = __half2float(g_wall2[(size_t)ea *384 + wcol]);
        float wb = __half2float(g_wall2[(size_t)ebx*384 + wcol]);
        float wc = __half2float(g_wall2[(size_t)ec *384 + wcol]);
        float wd = __half2float(g_wall2[(size_t)edx*384 + wcol]);
        float sa = f0p[g_src[ii  ]*32 + lane];
        float sb = f0p[g_src[ii+1]*32 + lane];
        float sc = f0p[g_src[ii+2]*32 + lane];
        float sd = f0p[g_src[ii+3]*32 + lane];
        float wsa = wa*sa, wsb = wb*sb, wsc = wc*sc, wsd = wd*sd;
        const float* pa = &g_sh2[(size_t)(ii  )*16 + shoff];
        const float* pb = &g_sh2[(size_t)(ii+1)*16 + shoff];
        const float* pc = &g_sh2[(size_t)(ii+2)*16 + shoff];
        const float* pd = &g_sh2[(size_t)(ii+3)*16 + shoff];
        #pragma unroll
        for (int m = 0; m < dim; m++)
            acc[m] += wsa*pa[m] + wsb*pb[m] + wsc*pc[m] + wsd*pd[m];
    }
    #pragma unroll 1
    for (; ii < e1; ii++) {
        int e = g_eid[ii];
        float w = __half2float(g_wall2[(size_t)e*384 + wcol]);
        float s = f0p[g_src[ii]*32 + lane];
        float ws = w*s;
        const float* shp = &g_sh2[(size_t)ii*16 + shoff];
        #pragma unroll
        for (int m = 0; m < dim; m++) acc[m] += ws*shp[m];
    }
    #pragma unroll
    for (int m = 0; m < dim; m++) s_agg[off + lane*dim + m] = acc[m];
    __syncwarp();

    float o[dim];
    #pragma unroll
    for (int m = 0; m < dim; m++) o[m] = 0.f;
    const float* swp = sw + (size_t)((t*4 + LVAL)*32)*32;
    const float* mwp = mw + (size_t)((t*4 + LVAL)*32)*32;
    if (LVAL > 0 && !uself) {
        // t == 0: f[l>0] is identically zero -> message term only
        #pragma unroll 4
        for (int c = 0; c < 32; c++) {
            float wmv = mwp[c*32 + lane];
            #pragma unroll
            for (int m = 0; m < dim; m++)
                o[m] += s_agg[off + c*dim + m]*wmv;
        }
    } else {
        #pragma unroll 4
        for (int c = 0; c < 32; c++) {
            float wsv = swp[c*32 + lane];
            float wmv = mwp[c*32 + lane];
            #pragma unroll
            for (int m = 0; m < dim; m++)
                o[m] += s_f[off + c*dim + m]*wsv + s_agg[off + c*dim + m]*wmv;
        }
    }
    #pragma unroll
    for (int m = 0; m < dim; m++) s_new[off + lane*dim + m] = o[m];
}

__global__ void k_layer(int t,
                        const float* __restrict__ sw, const float* __restrict__ mw,
                        const float* __restrict__ gw,
                        float* __restrict__ outp) {
    const float* fp  = (t == 1) ? g_fb : g_fa;
    float* fn        = (t == 0) ? g_fb : ((t == 1) ? g_fa : outp);
    const float* f0p = (t == 1) ? g_f0b : g_f0a;
    float* f0n       = (t == 1) ? g_f0a : g_f0b;

    __shared__ float s_f[FD], s_agg[FD], s_new[FD], s_gate[32];
    int n = blockIdx.x;
    int tid = threadIdx.x, l = tid >> 5, lane = tid & 31;

    if (t == 0) {
        #pragma unroll
        for (int k = 0; k < 4; k++) {
            int idx = tid + k*128;
            s_f[idx] = (idx < 32) ? g_f0a[n*32 + idx] : 0.f;
        }
    } else {
        #pragma unroll
        for (int k = 0; k < 4; k++)
            s_f[tid + k*128] = fp[(size_t)n*FD + tid + k*128];
    }

    int e0 = g_off[n], e1 = g_off[n+1];
    __syncthreads();

    bool uself = (t != 0);
    switch (l) {
        case 0: layer_warp<0>(t, lane, e0, e1, uself, f0p, sw, mw, s_f, s_agg, s_new); break;
        case 1: layer_warp<1>(t, lane, e0, e1, uself, f0p, sw, mw, s_f, s_agg, s_new); break;
        case 2: layer_warp<2>(t, lane, e0, e1, uself, f0p, sw, mw, s_f, s_agg, s_new); break;
        default: layer_warp<3>(t, lane, e0, e1, uself, f0p, sw, mw, s_f, s_agg, s_new); break;
    }
    __syncthreads();

    if (l == 0) {
        float g = 0.f;
        #pragma unroll 4
        for (int c = 0; c < 32; c++)
            g += s_new[c] * gw[(t*32 + c)*32 + lane];
        s_gate[lane] = 1.0f / (1.0f + expf(-g));
    }
    __syncthreads();

    #pragma unroll
    for (int k = 0; k < 4; k++) {
        int idx = tid + k*128;
        float v = s_new[idx];
        float outv;
        if (idx < 32) {
            outv = v / (1.0f + expf(-v));
            f0n[n*32 + idx] = outv;
        } else {
            int d;
            if (idx < 128)      d = (idx - 32) / 3;
            else if (idx < 288) d = (idx - 128) / 5;
            else                d = (idx - 288) / 7;
            outv = v * s_gate[d];
        }
        fn[(size_t)n*FD + idx] = outv;
    }
}

// ---------------- edge output: 2 edges per 256-thread block, float4 stores ----------------
__global__ void k_edge_out(const int* __restrict__ ei, float* __restrict__ out) {
    __shared__ float s_g[2][32], s_sh[2][16], s_ew[2][128];
    int tid = threadIdx.x;
    int half = tid >> 7, t = tid & 127;
    int e = blockIdx.x*2 + half;
    int sn = ei[e], dn = ei[EE + e];
    if (t < 32)
        s_g[half][t] = g_f0b[sn*32 + t] + g_f0b[dn*32 + t];
    else if (t < 48)
        s_sh[half][t - 32] = g_sh[(size_t)e*16 + (t - 32)];
    s_ew[half][t] = __half2float(g_ew2[(size_t)e*128 + t]);
    __syncthreads();

    float* orow = out + (size_t)(NN + e)*FD;
    int idx0 = t*4;
    float4 v;
    float* pv = &v.x;
    #pragma unroll
    for (int j = 0; j < 4; j++) {
        int idx = idx0 + j;
        int l, c, m;
        if (idx < 32)       { l = 0; c = idx;       m = 0; }
        else if (idx < 128) { int r = idx - 32;  l = 1; c = r/3; m = r - 3*c; }
        else if (idx < 288) { int r = idx - 128; l = 2; c = r/5; m = r - 5*c; }
        else                { int r = idx - 288; l = 3; c = r/7; m = r - 7*c; }
        pv[j] = s_ew[half][l*32 + c] * s_g[half][c] * s_sh[half][l*l + m];
    }
    *(float4*)&orow[idx0] = v;
}

// ---------------- launch ----------------
extern "C" void kernel_launch(void* const* d_in, const int* in_sizes, int n_in,
                              void* d_out, int out_size) {
    const float* pos        = (const float*)d_in[0];
    const float* node_embed = (const float*)d_in[1];
    const float* rw1        = (const float*)d_in[2];
    const float* rb1        = (const float*)d_in[3];
    const float* rw2        = (const float*)d_in[4];
    const float* rb2        = (const float*)d_in[5];
    const float* self_w     = (const float*)d_in[6];
    const float* msg_w      = (const float*)d_in[7];
    const float* gate_w     = (const float*)d_in[8];
    const float* edge_w     = (const float*)d_in[9];
    const float* edge_b     = (const float*)d_in[10];
    const int*   species    = (const int*)d_in[11];
    const int*   ei         = (const int*)d_in[12];
    float* out = (float*)d_out;

    cudaFuncSetAttribute(k_geomh, cudaFuncAttributeMaxDynamicSharedMemorySize, GEOMH_SMEM);
    cudaFuncSetAttribute(k_gemm, cudaFuncAttributeMaxDynamicSharedMemorySize, GEMM_SMEM);

    // slot 0,1: CSR front
    k_zero<<<(NN+255)/256, 256>>>();
    k_hist<<<(EE+255)/256, 256>>>(ei);

    // slot 2: fused geometry + radial + MLP1 (packed output)
    k_geomh<<<EE/128, 256, GEOMH_SMEM>>>(pos, rw1, rb1, ei);

    // slot 3 (profiled): GEMM2 -> g_wall2 + g_ew2 (edge order, fp16)
    dim3 gg(EE/128, 4);
    k_gemm<<<gg, 256, GEMM_SMEM>>>(rw2, edge_w, rb2, edge_b);

    // slot 4,5: CSR scan + fill (eid/src/sh2)
    k_scan<<<1, 1024>>>();
    k_fill<<<(EE+255)/256, 256>>>(ei);

    // compact node features
    k_init<<<(NN*CC + 255)/256, 256>>>(node_embed, species);

    // 3 message-passing layers; last writes node rows of d_out directly
    for (int t = 0; t < 3; t++)
        k_layer<<<NN, 128>>>(t, self_w, msg_w, gate_w, out);

    // edge rows of d_out
    k_edge_out<<<EE/2, 256>>>(ei, out);
}

// round 14
// speedup vs baseline: 1.5151x; 1.5151x over previous
#include <cuda_runtime.h>
#include <cuda_fp16.h>
#include <math.h>
#include <cstdint>

#define NN 10000
#define EE 160000
#define CC 32
#define NB 128
#define HH 64
#define FD 512   // C * (1+3+5+7)

typedef unsigned long long u64t;
typedef ulonglong2 u642;

// ---------------- scratch (device globals; no allocation) ----------------
__device__ u64t   g_hp[(size_t)EE*32];     // 41 MB  : hidden, packed m-pair layout [b][k][mp]
__device__ float  g_sh[(size_t)EE*16];     // 10 MB  : sph harmonics, edge order
__device__ float  g_sh2[(size_t)EE*16];    // 10 MB  : sph harmonics, CSR order
__device__ __half g_wall2[(size_t)EE*384]; // 123 MB : layer weights, edge order, fp16
__device__ __half g_ew2[(size_t)EE*128];   // 41 MB  : edge-out weights, edge order, fp16
__device__ float  g_fa[(size_t)NN*FD];     // 20 MB  : node features buf A
__device__ float  g_fb[(size_t)NN*FD];     // 20 MB  : node features buf B
__device__ float  g_f0a[(size_t)NN*CC];    // 1.28 MB: compact f0 buf A
__device__ float  g_f0b[(size_t)NN*CC];    // 1.28 MB: compact f0 buf B
__device__ int    g_cnt[NN];
__device__ int    g_cnt2[NN];
__device__ int    g_off[NN+1];
__device__ int    g_eid[EE];               // CSR position -> edge
__device__ int    g_src[EE];               // CSR position -> src node

// ---------------- packed fp32 helpers ----------------
__device__ __forceinline__ u64t pack2(float v) {
    u64t r; asm("mov.b64 %0, {%1, %1};" : "=l"(r) : "f"(v)); return r;
}
__device__ __forceinline__ u64t pack2two(float lo, float hi) {
    u64t r; asm("mov.b64 %0, {%1, %2};" : "=l"(r) : "f"(lo), "f"(hi)); return r;
}
__device__ __forceinline__ void unpack2(u64t v, float& lo, float& hi) {
    asm("mov.b64 {%0, %1}, %2;" : "=f"(lo), "=f"(hi) : "l"(v));
}
__device__ __forceinline__ void ffma2(u64t& d, u64t a, u64t b) {
    asm("fma.rn.f32x2 %0, %1, %2, %0;" : "+l"(d) : "l"(a), "l"(b));
}

// ---------------- CSR build ----------------
__global__ void k_zero() {
    int i = blockIdx.x*blockDim.x + threadIdx.x;
    if (i < NN) { g_cnt[i] = 0; g_cnt2[i] = 0; }
}

__global__ void k_hist(const int* __restrict__ ei) {
    int e = blockIdx.x*blockDim.x + threadIdx.x;
    if (e < EE) atomicAdd(&g_cnt[ei[EE + e]], 1);
}

// one-pass parallel scan: 1024 threads, 10 contiguous elems each (NN = 1000*10)
__global__ void k_scan() {
    __shared__ int wsum[32];
    int t = threadIdx.x;
    int lane = t & 31, wid = t >> 5;
    int base = t*10;
    int loc[10];
    int s = 0;
    if (t < 1000) {
        #pragma unroll
        for (int j = 0; j < 10; j++) { s += g_cnt[base + j]; loc[j] = s; }
    }
    int v = s;
    #pragma unroll
    for (int o = 1; o < 32; o <<= 1) {
        int u = __shfl_up_sync(0xFFFFFFFF, v, o);
        if (lane >= o) v += u;
    }
    if (lane == 31) wsum[wid] = v;
    __syncthreads();
    if (wid == 0) {
        int w = wsum[lane];
        #pragma unroll
        for (int o = 1; o < 32; o <<= 1) {
            int u = __shfl_up_sync(0xFFFFFFFF, w, o);
            if (lane >= o) w += u;
        }
        wsum[lane] = w;
    }
    __syncthreads();
    int excl = v - s + (wid > 0 ? wsum[wid-1] : 0);
    if (t < 1000) {
        #pragma unroll
        for (int j = 0; j < 10; j++) g_off[base + j + 1] = excl + loc[j];
    }
    if (t == 0) g_off[0] = 0;
}

// fill: eid/src permutation + CSR-ordered copy of sh
__global__ void k_fill(const int* __restrict__ ei) {
    int e = blockIdx.x*blockDim.x + threadIdx.x;
    if (e < EE) {
        int d = ei[EE + e];
        int p = atomicAdd(&g_cnt2[d], 1);
        int slot = g_off[d] + p;
        g_eid[slot] = e;
        g_src[slot] = ei[e];
        const float4* src = (const float4*)&g_sh[(size_t)e*16];
        float4* dst = (float4*)&g_sh2[(size_t)slot*16];
        dst[0] = src[0]; dst[1] = src[1]; dst[2] = src[2]; dst[3] = src[3];
    }
}

// ---------------- fused: geometry + sh + radial basis + MLP1 (f32x2, 128 edges/block) ----
// output: g_hp in packed m-pair layout (k-major) for zero-transpose GEMM staging
#define GEOMH_SMEM 99328
__global__ void k_geomh(const float* __restrict__ pos, const float* __restrict__ rw1,
                        const float* __restrict__ rb1, const int* __restrict__ ei) {
    extern __shared__ char smem[];
    float* rb_s = (float*)smem;
    float* b1_s = (float*)(smem + 65536);
    float* su   = (float*)(smem + 98304);
    float* ss   = (float*)(smem + 98816);
    int tid = threadIdx.x;
    int eb = blockIdx.x*128;

    if (tid < 128) {
        int e = eb + tid;
        int sn = ei[e], dn = ei[EE + e];
        float vx = pos[dn*3+0] - pos[sn*3+0];
        float vy = pos[dn*3+1] - pos[sn*3+1];
        float vz = pos[dn*3+2] - pos[sn*3+2];
        float r2 = vx*vx + vy*vy + vz*vz + 1e-12f;
        float r  = sqrtf(r2);
        float inv_r = 1.0f / r;
        float x = vx*inv_r, y = vy*inv_r, z = vz*inv_r;

        const float s3  = 1.7320508075688772f;
        const float s15 = 3.872983346207417f;
        const float s5h = 1.118033988749895f;
        const float s15h= 1.9364916731037085f;
        const float c1  = 2.091650066335189f;
        const float c2  = 10.246950765959598f;
        const float c3  = 1.6201851746019651f;
        const float c4  = 1.3228756555322954f;
        const float c5  = 5.123475382979799f;
        float4 q0 = make_float4(1.0f, s3*x, s3*y, s3*z);
        float4 q1 = make_float4(s15*x*y, s15*y*z, s5h*(3.0f*z*z - 1.0f), s15*x*z);
        float4 q2 = make_float4(s15h*(x*x - y*y), c1*y*(3.0f*x*x - y*y), c2*x*y*z,
                                c3*y*(5.0f*z*z - 1.0f));
        float4 q3 = make_float4(c4*(5.0f*z*z*z - 3.0f*z), c3*x*(5.0f*z*z - 1.0f),
                                c5*z*(x*x - y*y), c1*x*(x*x - 3.0f*y*y));
        float4* shp = (float4*)&g_sh[(size_t)e*16];
        shp[0] = q0; shp[1] = q1; shp[2] = q2; shp[3] = q3;

        float u = fminf(r * 0.2f, 1.0f);
        float env = 0.5f * (cospif(u) + 1.0f);
        su[tid] = u;
        ss[tid] = env * 0.6324555320336759f * inv_r;
    }
    {
        const float4* src = (const float4*)rw1;
        float4* dst = (float4*)b1_s;
        #pragma unroll
        for (int i = tid; i < 2048; i += 256) dst[i] = src[i];
    }
    __syncthreads();

    {
        int e = tid & 127, kh = tid >> 7;
        float u = su[e], sc = ss[e];
        #pragma unroll 4
        for (int j = 0; j < 64; j++) {
            int k = kh*64 + j;
            rb_s[k*128 + e] = sc * sinpif((float)(k+1) * u);
        }
    }
    __syncthreads();

    int ty = tid >> 4, tx = tid & 15;
    u64t acc[4][4];
    #pragma unroll
    for (int p = 0; p < 4; p++)
        #pragma unroll
        for (int c = 0; c < 4; c++) acc[p][c] = 0ull;

    #pragma unroll 4
    for (int k = 0; k < 128; k++) {
        u64t ap[4];
        #pragma unroll
        for (int p = 0; p < 4; p++)
            ap[p] = *(const u64t*)&rb_s[k*128 + ty*8 + 2*p];
        float4 bv = *(const float4*)&b1_s[k*64 + tx*4];
        u64t bp[4] = {pack2(bv.x), pack2(bv.y), pack2(bv.z), pack2(bv.w)};
        #pragma unroll
        for (int p = 0; p < 4; p++)
            #pragma unroll
            for (int c = 0; c < 4; c++)
                ffma2(acc[p][c], ap[p], bp[c]);
    }

    // silu + bias, keep in registers
    float4 bias = *(const float4*)&rb1[tx*4];
    float bb[4] = {bias.x, bias.y, bias.z, bias.w};
    float lov[4][4], hiv[4][4];
    #pragma unroll
    for (int p = 0; p < 4; p++) {
        #pragma unroll
        for (int c = 0; c < 4; c++) {
            float lo, hi;
            unpack2(acc[p][c], lo, hi);
            float a = lo + bb[c];
            float b = hi + bb[c];
            lov[p][c] = a / (1.0f + expf(-a));
            hiv[p][c] = b / (1.0f + expf(-b));
        }
    }

    // transpose bounce through smem (rb_s dead) into packed m-pair layout, stride 66
    __syncthreads();
    {
        u64t* pk = (u64t*)smem;
        #pragma unroll
        for (int p = 0; p < 4; p++) {
            int mp = ty*4 + p;
            #pragma unroll
            for (int c = 0; c < 4; c++) {
                int k = tx*4 + c;
                pk[k*66 + mp] = pack2two(lov[p][c], hiv[p][c]);
            }
        }
    }
    __syncthreads();
    {
        const u64t* pk = (const u64t*)smem;
        u642* dst = (u642*)&g_hp[(size_t)blockIdx.x*4096];
        #pragma unroll
        for (int q = 0; q < 8; q++) {
            int li = tid + q*256;
            int k = li >> 5, mq = li & 31;
            dst[li] = *(const u642*)&pk[k*66 + mq*2];
        }
    }
}

// ---------------- GEMM2 (f32x2, fp16 out; zero-transpose A staging; LDS.128 A) ----
#define AST 66
#define BST 132
#define GEMM_SMEM (64*AST*8 + 64*BST*4)   // 33792 + 33792 = 67584
__global__ void k_gemm(const float* __restrict__ rw2, const float* __restrict__ edge_w,
                       const float* __restrict__ rb2, const float* __restrict__ edge_b) {
    extern __shared__ char smg[];
    u64t*  As2 = (u64t*)smg;
    float* Bs  = (float*)(smg + 64*AST*8);
    int tid = threadIdx.x;
    int bx = blockIdx.x, by = blockIdx.y;
    int eb = bx*128;

    // stage A: pure coalesced copy, no transpose
    {
        const u642* src = (const u642*)&g_hp[(size_t)bx*4096];
        #pragma unroll
        for (int q = 0; q < 8; q++) {
            int li = tid + q*256;
            int k = li >> 5, mq = li & 31;
            *(u642*)&As2[k*AST + mq*2] = src[li];
        }
    }
    #pragma unroll
    for (int p = 0; p < 8; p++) {
        int li = tid + p*256;
        int k = li >> 5, n4 = li & 31;
        int jg = by*128 + n4*4;
        float4 v = (jg < 384) ? *(const float4*)&rw2[k*384 + jg]
                              : *(const float4*)&edge_w[k*128 + (jg - 384)];
        *(float4*)&Bs[k*BST + n4*4] = v;
    }
    __syncthreads();

    int my = tid >> 4, nx = tid & 15;
    u64t acc[4][8];
    #pragma unroll
    for (int i = 0; i < 4; i++)
        #pragma unroll
        for (int n = 0; n < 8; n++) acc[i][n] = 0ull;

    #pragma unroll 8
    for (int k = 0; k < 64; k++) {
        u642 A0 = *(const u642*)&As2[k*AST + my*4];
        u642 A1 = *(const u642*)&As2[k*AST + my*4 + 2];
        u64t a[4] = {A0.x, A0.y, A1.x, A1.y};
        float4 b0 = *(const float4*)&Bs[k*BST + nx*8];
        float4 b1 = *(const float4*)&Bs[k*BST + nx*8 + 4];
        u64t bp[8] = {pack2(b0.x), pack2(b0.y), pack2(b0.z), pack2(b0.w),
                      pack2(b1.x), pack2(b1.y), pack2(b1.z), pack2(b1.w)};
        #pragma unroll
        for (int i = 0; i < 4; i++)
            #pragma unroll
            for (int n = 0; n < 8; n++)
                ffma2(acc[i][n], a[i], bp[n]);
    }

    float bj[8];
    #pragma unroll
    for (int n = 0; n < 8; n++) {
        int jg = by*128 + nx*8 + n;
        bj[n] = (jg < 384) ? rb2[jg] : edge_b[jg - 384];
    }

    #pragma unroll
    for (int i = 0; i < 4; i++) {
        float lo[8], hi[8];
        #pragma unroll
        for (int n = 0; n < 8; n++) {
            unpack2(acc[i][n], lo[n], hi[n]);
            lo[n] += bj[n]; hi[n] += bj[n];
        }
        int er0 = eb + my*8 + 2*i;
        __half* dst;
        size_t r0, r1;
        if (by < 3) {
            dst = g_wall2;
            r0 = (size_t)er0*384       + by*128 + nx*8;
            r1 = (size_t)(er0 + 1)*384 + by*128 + nx*8;
        } else {
            dst = g_ew2;
            r0 = (size_t)er0*128       + nx*8;
            r1 = (size_t)(er0 + 1)*128 + nx*8;
        }
        __half2 a0 = __floats2half2_rn(lo[0], lo[1]);
        __half2 a1 = __floats2half2_rn(lo[2], lo[3]);
        __half2 a2 = __floats2half2_rn(lo[4], lo[5]);
        __half2 a3 = __floats2half2_rn(lo[6], lo[7]);
        uint4 u0;
        u0.x = *(unsigned*)&a0; u0.y = *(unsigned*)&a1;
        u0.z = *(unsigned*)&a2; u0.w = *(unsigned*)&a3;
        *(uint4*)&dst[r0] = u0;
        __half2 c0 = __floats2half2_rn(hi[0], hi[1]);
        __half2 c1 = __floats2half2_rn(hi[2], hi[3]);
        __half2 c2 = __floats2half2_rn(hi[4], hi[5]);
        __half2 c3 = __floats2half2_rn(hi[6], hi[7]);
        uint4 u1;
        u1.x = *(unsigned*)&c0; u1.y = *(unsigned*)&c1;
        u1.z = *(unsigned*)&c2; u1.w = *(unsigned*)&c3;
        *(uint4*)&dst[r1] = u1;
    }
}

// ---------------- node feature init (compact f0 only) ----------------
__global__ void k_init(const float* __restrict__ node_embed, const int* __restrict__ species) {
    int i = blockIdx.x*blockDim.x + threadIdx.x;
    if (i < NN*CC) {
        int n = i >> 5, idx = i & 31;
        g_f0a[i] = node_embed[species[n]*32 + idx];
    }
}

// ---------------- one message-passing layer (round-8 structure, 128 threads) ----------
template<int LVAL>
__device__ __forceinline__ void layer_warp(int t, int lane, int e0, int e1, bool uself,
                                           const float* __restrict__ f0p,
                                           const float* __restrict__ sw,
                                           const float* __restrict__ mw,
                                           const float* s_f, float* s_agg, float* s_new) {
    constexpr int dim = 2*LVAL + 1;
    constexpr int off = 32*LVAL*LVAL;
    constexpr int shoff = LVAL*LVAL;
    const int wcol = t*128 + LVAL*32 + lane;

    float acc[dim];
    #pragma unroll
    for (int m = 0; m < dim; m++) acc[m] = 0.f;

    int ii = e0;
    #pragma unroll 1
    for (; ii + 4 <= e1; ii += 4) {
        int ea = g_eid[ii],   ebx = g_eid[ii+1];
        int ec = g_eid[ii+2], edx = g_eid[ii+3];
        float wa = __half2float(g_wall2[(size_t)ea *384 + wcol]);
        float wb = __half2float(g_wall2[(size_t)ebx*384 + wcol]);
        float wc = __half2float(g_wall2[(size_t)ec *384 + wcol]);
        float wd = __half2float(g_wall2[(size_t)edx*384 + wcol]);
        float sa = f0p[g_src[ii  ]*32 + lane];
        float sb = f0p[g_src[ii+1]*32 + lane];
        float sc = f0p[g_src[ii+2]*32 + lane];
        float sd = f0p[g_src[ii+3]*32 + lane];
        float wsa = wa*sa, wsb = wb*sb, wsc = wc*sc, wsd = wd*sd;
        const float* pa = &g_sh2[(size_t)(ii  )*16 + shoff];
        const float* pb = &g_sh2[(size_t)(ii+1)*16 + shoff];
        const float* pc = &g_sh2[(size_t)(ii+2)*16 + shoff];
        const float* pd = &g_sh2[(size_t)(ii+3)*16 + shoff];
        #pragma unroll
        for (int m = 0; m < dim; m++)
            acc[m] += wsa*pa[m] + wsb*pb[m] + wsc*pc[m] + wsd*pd[m];
    }
    #pragma unroll 1
    for (; ii < e1; ii++) {
        int e = g_eid[ii];
        float w = __half2float(g_wall2[(size_t)e*384 + wcol]);
        float s = f0p[g_src[ii]*32 + lane];
        float ws = w*s;
        const float* shp = &g_sh2[(size_t)ii*16 + shoff];
        #pragma unroll
        for (int m = 0; m < dim; m++) acc[m] += ws*shp[m];
    }
    #pragma unroll
    for (int m = 0; m < dim; m++) s_agg[off + lane*dim + m] = acc[m];
    __syncwarp();

    float o[dim];
    #pragma unroll
    for (int m = 0; m < dim; m++) o[m] = 0.f;
    const float* swp = sw + (size_t)((t*4 + LVAL)*32)*32;
    const float* mwp = mw + (size_t)((t*4 + LVAL)*32)*32;
    if (LVAL > 0 && !uself) {
        // t == 0: f[l>0] is identically zero -> message term only
        #pragma unroll 4
        for (int c = 0; c < 32; c++) {
            float wmv = mwp[c*32 + lane];
            #pragma unroll
            for (int m = 0; m < dim; m++)
                o[m] += s_agg[off + c*dim + m]*wmv;
        }
    } else {
        #pragma unroll 4
        for (int c = 0; c < 32; c++) {
            float wsv = swp[c*32 + lane];
            float wmv = mwp[c*32 + lane];
            #pragma unroll
            for (int m = 0; m < dim; m++)
                o[m] += s_f[off + c*dim + m]*wsv + s_agg[off + c*dim + m]*wmv;
        }
    }
    #pragma unroll
    for (int m = 0; m < dim; m++) s_new[off + lane*dim + m] = o[m];
}

__global__ void k_layer(int t,
                        const float* __restrict__ sw, const float* __restrict__ mw,
                        const float* __restrict__ gw,
                        float* __restrict__ outp) {
    const float* fp  = (t == 1) ? g_fb : g_fa;
    float* fn        = (t == 0) ? g_fb : ((t == 1) ? g_fa : outp);
    const float* f0p = (t == 1) ? g_f0b : g_f0a;
    float* f0n       = (t == 1) ? g_f0a : g_f0b;

    __shared__ float s_f[FD], s_agg[FD], s_new[FD], s_gate[32];
    int n = blockIdx.x;
    int tid = threadIdx.x, l = tid >> 5, lane = tid & 31;

    if (t == 0) {
        #pragma unroll
        for (int k = 0; k < 4; k++) {
            int idx = tid + k*128;
            s_f[idx] = (idx < 32) ? g_f0a[n*32 + idx] : 0.f;
        }
    } else {
        #pragma unroll
        for (int k = 0; k < 4; k++)
            s_f[tid + k*128] = fp[(size_t)n*FD + tid + k*128];
    }

    int e0 = g_off[n], e1 = g_off[n+1];
    __syncthreads();

    bool uself = (t != 0);
    switch (l) {
        case 0: layer_warp<0>(t, lane, e0, e1, uself, f0p, sw, mw, s_f, s_agg, s_new); break;
        case 1: layer_warp<1>(t, lane, e0, e1, uself, f0p, sw, mw, s_f, s_agg, s_new); break;
        case 2: layer_warp<2>(t, lane, e0, e1, uself, f0p, sw, mw, s_f, s_agg, s_new); break;
        default: layer_warp<3>(t, lane, e0, e1, uself, f0p, sw, mw, s_f, s_agg, s_new); break;
    }
    __syncthreads();

    if (l == 0) {
        float g = 0.f;
        #pragma unroll 4
        for (int c = 0; c < 32; c++)
            g += s_new[c] * gw[(t*32 + c)*32 + lane];
        s_gate[lane] = 1.0f / (1.0f + expf(-g));
    }
    __syncthreads();

    #pragma unroll
    for (int k = 0; k < 4; k++) {
        int idx = tid + k*128;
        float v = s_new[idx];
        float outv;
        if (idx < 32) {
            outv = v / (1.0f + expf(-v));
            f0n[n*32 + idx] = outv;
        } else {
            int d;
            if (idx < 128)      d = (idx - 32) / 3;
            else if (idx < 288) d = (idx - 128) / 5;
            else                d = (idx - 288) / 7;
            outv = v * s_gate[d];
        }
        fn[(size_t)n*FD + idx] = outv;
    }
}

// ---------------- edge output: 2 edges per 256-thread block, float4 stores ----------------
__global__ void k_edge_out(const int* __restrict__ ei, float* __restrict__ out) {
    __shared__ float s_g[2][32], s_sh[2][16], s_ew[2][128];
    int tid = threadIdx.x;
    int half = tid >> 7, t = tid & 127;
    int e = blockIdx.x*2 + half;
    int sn = ei[e], dn = ei[EE + e];
    if (t < 32)
        s_g[half][t] = g_f0b[sn*32 + t] + g_f0b[dn*32 + t];
    else if (t < 48)
        s_sh[half][t - 32] = g_sh[(size_t)e*16 + (t - 32)];
    s_ew[half][t] = __half2float(g_ew2[(size_t)e*128 + t]);
    __syncthreads();

    float* orow = out + (size_t)(NN + e)*FD;
    int idx0 = t*4;
    float4 v;
    float* pv = &v.x;
    #pragma unroll
    for (int j = 0; j < 4; j++) {
        int idx = idx0 + j;
        int l, c, m;
        if (idx < 32)       { l = 0; c = idx;       m = 0; }
        else if (idx < 128) { int r = idx - 32;  l = 1; c = r/3; m = r - 3*c; }
        else if (idx < 288) { int r = idx - 128; l = 2; c = r/5; m = r - 5*c; }
        else                { int r = idx - 288; l = 3; c = r/7; m = r - 7*c; }
        pv[j] = s_ew[half][l*32 + c] * s_g[half][c] * s_sh[half][l*l + m];
    }
    *(float4*)&orow[idx0] = v;
}

// ---------------- launch ----------------
extern "C" void kernel_launch(void* const* d_in, const int* in_sizes, int n_in,
                              void* d_out, int out_size) {
    const float* pos        = (const float*)d_in[0];
    const float* node_embed = (const float*)d_in[1];
    const float* rw1        = (const float*)d_in[2];
    const float* rb1        = (const float*)d_in[3];
    const float* rw2        = (const float*)d_in[4];
    const float* rb2        = (const float*)d_in[5];
    const float* self_w     = (const float*)d_in[6];
    const float* msg_w      = (const float*)d_in[7];
    const float* gate_w     = (const float*)d_in[8];
    const float* edge_w     = (const float*)d_in[9];
    const float* edge_b     = (const float*)d_in[10];
    const int*   species    = (const int*)d_in[11];
    const int*   ei         = (const int*)d_in[12];
    float* out = (float*)d_out;

    cudaFuncSetAttribute(k_geomh, cudaFuncAttributeMaxDynamicSharedMemorySize, GEOMH_SMEM);
    cudaFuncSetAttribute(k_gemm, cudaFuncAttributeMaxDynamicSharedMemorySize, GEMM_SMEM);

    // slot 0,1: CSR front
    k_zero<<<(NN+255)/256, 256>>>();
    k_hist<<<(EE+255)/256, 256>>>(ei);

    // slot 2: fused geometry + radial + MLP1 (packed output)
    k_geomh<<<EE/128, 256, GEOMH_SMEM>>>(pos, rw1, rb1, ei);

    // slot 3 (profiled): GEMM2 -> g_wall2 + g_ew2 (edge order, fp16)
    dim3 gg(EE/128, 4);
    k_gemm<<<gg, 256, GEMM_SMEM>>>(rw2, edge_w, rb2, edge_b);

    // slot 4,5: CSR scan + fill (eid/src/sh2)
    k_scan<<<1, 1024>>>();
    k_fill<<<(EE+255)/256, 256>>>(ei);

    // compact node features
    k_init<<<(NN*CC + 255)/256, 256>>>(node_embed, species);

    // 3 message-passing layers; last writes node rows of d_out directly
    for (int t = 0; t < 3; t++)
        k_layer<<<NN, 128>>>(t, self_w, msg_w, gate_w, out);

    // edge rows of d_out
    k_edge_out<<<EE/2, 256>>>(ei, out);
}

// round 15
// speedup vs baseline: 1.6608x; 1.0962x over previous
#include <cuda_runtime.h>
#include <cuda_fp16.h>
#include <math.h>
#include <cstdint>

#define NN 10000
#define EE 160000
#define CC 32
#define NB 128
#define HH 64
#define FD 512   // C * (1+3+5+7)

typedef unsigned long long u64t;
typedef ulonglong2 u642;

// ---------------- scratch (device globals; no allocation) ----------------
__device__ u64t   g_hp[(size_t)EE*32];     // 41 MB  : hidden, packed m-pair layout [b][k][mp]
__device__ float  g_sh[(size_t)EE*16];     // 10 MB  : sph harmonics, edge order
__device__ float  g_sh2[(size_t)EE*16];    // 10 MB  : sph harmonics, CSR order
__device__ __half g_wall2[(size_t)EE*384]; // 123 MB : layer weights, edge order, fp16
__device__ __half g_ew2[(size_t)EE*128];   // 41 MB  : edge-out weights, edge order, fp16
__device__ float  g_fa[(size_t)NN*FD];     // 20 MB  : node features buf A
__device__ float  g_fb[(size_t)NN*FD];     // 20 MB  : node features buf B
__device__ float  g_f0a[(size_t)NN*CC];    // 1.28 MB: compact f0 buf A
__device__ float  g_f0b[(size_t)NN*CC];    // 1.28 MB: compact f0 buf B
__device__ int    g_cnt[NN];
__device__ int    g_cnt2[NN];
__device__ int    g_off[NN+1];
__device__ int    g_eid[EE];               // CSR position -> edge
__device__ int    g_src[EE];               // CSR position -> src node

// ---------------- packed fp32 helpers ----------------
__device__ __forceinline__ u64t pack2(float v) {
    u64t r; asm("mov.b64 %0, {%1, %1};" : "=l"(r) : "f"(v)); return r;
}
__device__ __forceinline__ u64t pack2two(float lo, float hi) {
    u64t r; asm("mov.b64 %0, {%1, %2};" : "=l"(r) : "f"(lo), "f"(hi)); return r;
}
__device__ __forceinline__ void unpack2(u64t v, float& lo, float& hi) {
    asm("mov.b64 {%0, %1}, %2;" : "=f"(lo), "=f"(hi) : "l"(v));
}
__device__ __forceinline__ void ffma2(u64t& d, u64t a, u64t b) {
    asm("fma.rn.f32x2 %0, %1, %2, %0;" : "+l"(d) : "l"(a), "l"(b));
}

// ---------------- CSR build ----------------
__global__ void k_zero() {
    int i = blockIdx.x*blockDim.x + threadIdx.x;
    if (i < NN) { g_cnt[i] = 0; g_cnt2[i] = 0; }
}

__global__ void k_hist(const int* __restrict__ ei) {
    int e = blockIdx.x*blockDim.x + threadIdx.x;
    if (e < EE) atomicAdd(&g_cnt[ei[EE + e]], 1);
}

// one-pass parallel scan: 1024 threads, 10 contiguous elems each (NN = 1000*10)
__global__ void k_scan() {
    __shared__ int wsum[32];
    int t = threadIdx.x;
    int lane = t & 31, wid = t >> 5;
    int base = t*10;
    int loc[10];
    int s = 0;
    if (t < 1000) {
        #pragma unroll
        for (int j = 0; j < 10; j++) { s += g_cnt[base + j]; loc[j] = s; }
    }
    int v = s;
    #pragma unroll
    for (int o = 1; o < 32; o <<= 1) {
        int u = __shfl_up_sync(0xFFFFFFFF, v, o);
        if (lane >= o) v += u;
    }
    if (lane == 31) wsum[wid] = v;
    __syncthreads();
    if (wid == 0) {
        int w = wsum[lane];
        #pragma unroll
        for (int o = 1; o < 32; o <<= 1) {
            int u = __shfl_up_sync(0xFFFFFFFF, w, o);
            if (lane >= o) w += u;
        }
        wsum[lane] = w;
    }
    __syncthreads();
    int excl = v - s + (wid > 0 ? wsum[wid-1] : 0);
    if (t < 1000) {
        #pragma unroll
        for (int j = 0; j < 10; j++) g_off[base + j + 1] = excl + loc[j];
    }
    if (t == 0) g_off[0] = 0;
}

// fill: eid/src permutation + CSR-ordered copy of sh
__global__ void k_fill(const int* __restrict__ ei) {
    int e = blockIdx.x*blockDim.x + threadIdx.x;
    if (e < EE) {
        int d = ei[EE + e];
        int p = atomicAdd(&g_cnt2[d], 1);
        int slot = g_off[d] + p;
        g_eid[slot] = e;
        g_src[slot] = ei[e];
        const float4* src = (const float4*)&g_sh[(size_t)e*16];
        float4* dst = (float4*)&g_sh2[(size_t)slot*16];
        dst[0] = src[0]; dst[1] = src[1]; dst[2] = src[2]; dst[3] = src[3];
    }
}

// ---------------- fused: geometry + sh + radial basis + MLP1 (f32x2, 128 edges/block) ----
// output: g_hp in packed m-pair layout (k-major) for zero-transpose GEMM staging
#define GEOMH_SMEM 99328
__global__ void k_geomh(const float* __restrict__ pos, const float* __restrict__ rw1,
                        const float* __restrict__ rb1, const int* __restrict__ ei) {
    extern __shared__ char smem[];
    float* rb_s = (float*)smem;
    float* b1_s = (float*)(smem + 65536);
    float* su   = (float*)(smem + 98304);
    float* ss   = (float*)(smem + 98816);
    int tid = threadIdx.x;
    int eb = blockIdx.x*128;

    if (tid < 128) {
        int e = eb + tid;
        int sn = ei[e], dn = ei[EE + e];
        float vx = pos[dn*3+0] - pos[sn*3+0];
        float vy = pos[dn*3+1] - pos[sn*3+1];
        float vz = pos[dn*3+2] - pos[sn*3+2];
        float r2 = vx*vx + vy*vy + vz*vz + 1e-12f;
        float r  = sqrtf(r2);
        float inv_r = 1.0f / r;
        float x = vx*inv_r, y = vy*inv_r, z = vz*inv_r;

        const float s3  = 1.7320508075688772f;
        const float s15 = 3.872983346207417f;
        const float s5h = 1.118033988749895f;
        const float s15h= 1.9364916731037085f;
        const float c1  = 2.091650066335189f;
        const float c2  = 10.246950765959598f;
        const float c3  = 1.6201851746019651f;
        const float c4  = 1.3228756555322954f;
        const float c5  = 5.123475382979799f;
        float4 q0 = make_float4(1.0f, s3*x, s3*y, s3*z);
        float4 q1 = make_float4(s15*x*y, s15*y*z, s5h*(3.0f*z*z - 1.0f), s15*x*z);
        float4 q2 = make_float4(s15h*(x*x - y*y), c1*y*(3.0f*x*x - y*y), c2*x*y*z,
                                c3*y*(5.0f*z*z - 1.0f));
        float4 q3 = make_float4(c4*(5.0f*z*z*z - 3.0f*z), c3*x*(5.0f*z*z - 1.0f),
                                c5*z*(x*x - y*y), c1*x*(x*x - 3.0f*y*y));
        float4* shp = (float4*)&g_sh[(size_t)e*16];
        shp[0] = q0; shp[1] = q1; shp[2] = q2; shp[3] = q3;

        float u = fminf(r * 0.2f, 1.0f);
        float env = 0.5f * (cospif(u) + 1.0f);
        su[tid] = u;
        ss[tid] = env * 0.6324555320336759f * inv_r;
    }
    {
        const float4* src = (const float4*)rw1;
        float4* dst = (float4*)b1_s;
        #pragma unroll
        for (int i = tid; i < 2048; i += 256) dst[i] = src[i];
    }
    __syncthreads();

    {
        int e = tid & 127, kh = tid >> 7;
        float u = su[e], sc = ss[e];
        #pragma unroll 4
        for (int j = 0; j < 64; j++) {
            int k = kh*64 + j;
            rb_s[k*128 + e] = sc * sinpif((float)(k+1) * u);
        }
    }
    __syncthreads();

    int ty = tid >> 4, tx = tid & 15;
    u64t acc[4][4];
    #pragma unroll
    for (int p = 0; p < 4; p++)
        #pragma unroll
        for (int c = 0; c < 4; c++) acc[p][c] = 0ull;

    #pragma unroll 4
    for (int k = 0; k < 128; k++) {
        u64t ap[4];
        #pragma unroll
        for (int p = 0; p < 4; p++)
            ap[p] = *(const u64t*)&rb_s[k*128 + ty*8 + 2*p];
        float4 bv = *(const float4*)&b1_s[k*64 + tx*4];
        u64t bp[4] = {pack2(bv.x), pack2(bv.y), pack2(bv.z), pack2(bv.w)};
        #pragma unroll
        for (int p = 0; p < 4; p++)
            #pragma unroll
            for (int c = 0; c < 4; c++)
                ffma2(acc[p][c], ap[p], bp[c]);
    }

    // silu + bias, keep in registers
    float4 bias = *(const float4*)&rb1[tx*4];
    float bb[4] = {bias.x, bias.y, bias.z, bias.w};
    float lov[4][4], hiv[4][4];
    #pragma unroll
    for (int p = 0; p < 4; p++) {
        #pragma unroll
        for (int c = 0; c < 4; c++) {
            float lo, hi;
            unpack2(acc[p][c], lo, hi);
            float a = lo + bb[c];
            float b = hi + bb[c];
            lov[p][c] = a / (1.0f + expf(-a));
            hiv[p][c] = b / (1.0f + expf(-b));
        }
    }

    // transpose bounce through smem (rb_s dead) into packed m-pair layout, stride 66
    __syncthreads();
    {
        u64t* pk = (u64t*)smem;
        #pragma unroll
        for (int p = 0; p < 4; p++) {
            int mp = ty*4 + p;
            #pragma unroll
            for (int c = 0; c < 4; c++) {
                int k = tx*4 + c;
                pk[k*66 + mp] = pack2two(lov[p][c], hiv[p][c]);
            }
        }
    }
    __syncthreads();
    {
        const u64t* pk = (const u64t*)smem;
        u642* dst = (u642*)&g_hp[(size_t)blockIdx.x*4096];
        #pragma unroll
        for (int q = 0; q < 8; q++) {
            int li = tid + q*256;
            int k = li >> 5, mq = li & 31;
            dst[li] = *(const u642*)&pk[k*66 + mq*2];
        }
    }
}

// ---------------- GEMM2 (f32x2, fp16 out; zero-transpose A staging; LDS.128 A) ----
#define AST 66
#define BST 132
#define GEMM_SMEM (64*AST*8 + 64*BST*4)   // 33792 + 33792 = 67584
__global__ void k_gemm(const float* __restrict__ rw2, const float* __restrict__ edge_w,
                       const float* __restrict__ rb2, const float* __restrict__ edge_b) {
    extern __shared__ char smg[];
    u64t*  As2 = (u64t*)smg;
    float* Bs  = (float*)(smg + 64*AST*8);
    int tid = threadIdx.x;
    int bx = blockIdx.x, by = blockIdx.y;
    int eb = bx*128;

    // stage A: pure coalesced copy, no transpose
    {
        const u642* src = (const u642*)&g_hp[(size_t)bx*4096];
        #pragma unroll
        for (int q = 0; q < 8; q++) {
            int li = tid + q*256;
            int k = li >> 5, mq = li & 31;
            *(u642*)&As2[k*AST + mq*2] = src[li];
        }
    }
    #pragma unroll
    for (int p = 0; p < 8; p++) {
        int li = tid + p*256;
        int k = li >> 5, n4 = li & 31;
        int jg = by*128 + n4*4;
        float4 v = (jg < 384) ? *(const float4*)&rw2[k*384 + jg]
                              : *(const float4*)&edge_w[k*128 + (jg - 384)];
        *(float4*)&Bs[k*BST + n4*4] = v;
    }
    __syncthreads();

    int my = tid >> 4, nx = tid & 15;
    u64t acc[4][8];
    #pragma unroll
    for (int i = 0; i < 4; i++)
        #pragma unroll
        for (int n = 0; n < 8; n++) acc[i][n] = 0ull;

    #pragma unroll 8
    for (int k = 0; k < 64; k++) {
        u642 A0 = *(const u642*)&As2[k*AST + my*4];
        u642 A1 = *(const u642*)&As2[k*AST + my*4 + 2];
        u64t a[4] = {A0.x, A0.y, A1.x, A1.y};
        float4 b0 = *(const float4*)&Bs[k*BST + nx*8];
        float4 b1 = *(const float4*)&Bs[k*BST + nx*8 + 4];
        u64t bp[8] = {pack2(b0.x), pack2(b0.y), pack2(b0.z), pack2(b0.w),
                      pack2(b1.x), pack2(b1.y), pack2(b1.z), pack2(b1.w)};
        #pragma unroll
        for (int i = 0; i < 4; i++)
            #pragma unroll
            for (int n = 0; n < 8; n++)
                ffma2(acc[i][n], a[i], bp[n]);
    }

    float bj[8];
    #pragma unroll
    for (int n = 0; n < 8; n++) {
        int jg = by*128 + nx*8 + n;
        bj[n] = (jg < 384) ? rb2[jg] : edge_b[jg - 384];
    }

    #pragma unroll
    for (int i = 0; i < 4; i++) {
        float lo[8], hi[8];
        #pragma unroll
        for (int n = 0; n < 8; n++) {
            unpack2(acc[i][n], lo[n], hi[n]);
            lo[n] += bj[n]; hi[n] += bj[n];
        }
        int er0 = eb + my*8 + 2*i;
        __half* dst;
        size_t r0, r1;
        if (by < 3) {
            dst = g_wall2;
            r0 = (size_t)er0*384       + by*128 + nx*8;
            r1 = (size_t)(er0 + 1)*384 + by*128 + nx*8;
        } else {
            dst = g_ew2;
            r0 = (size_t)er0*128       + nx*8;
            r1 = (size_t)(er0 + 1)*128 + nx*8;
        }
        __half2 a0 = __floats2half2_rn(lo[0], lo[1]);
        __half2 a1 = __floats2half2_rn(lo[2], lo[3]);
        __half2 a2 = __floats2half2_rn(lo[4], lo[5]);
        __half2 a3 = __floats2half2_rn(lo[6], lo[7]);
        uint4 u0;
        u0.x = *(unsigned*)&a0; u0.y = *(unsigned*)&a1;
        u0.z = *(unsigned*)&a2; u0.w = *(unsigned*)&a3;
        *(uint4*)&dst[r0] = u0;
        __half2 c0 = __floats2half2_rn(hi[0], hi[1]);
        __half2 c1 = __floats2half2_rn(hi[2], hi[3]);
        __half2 c2 = __floats2half2_rn(hi[4], hi[5]);
        __half2 c3 = __floats2half2_rn(hi[6], hi[7]);
        uint4 u1;
        u1.x = *(unsigned*)&c0; u1.y = *(unsigned*)&c1;
        u1.z = *(unsigned*)&c2; u1.w = *(unsigned*)&c3;
        *(uint4*)&dst[r1] = u1;
    }
}

// ---------------- node feature init (compact f0 only) ----------------
__global__ void k_init(const float* __restrict__ node_embed, const int* __restrict__ species) {
    int i = blockIdx.x*blockDim.x + threadIdx.x;
    if (i < NN*CC) {
        int n = i >> 5, idx = i & 31;
        g_f0a[i] = node_embed[species[n]*32 + idx];
    }
}

// ---------------- layer gather over one prefetched chunk (no block barriers inside) ----
template<int LVAL>
__device__ __forceinline__ void gather_chunk(int wcol, int lane, int base, int cnt,
                                             const int* s_eid, const int* s_src,
                                             const float* __restrict__ f0p, float* acc) {
    constexpr int dim = 2*LVAL + 1;
    constexpr int shoff = LVAL*LVAL;
    int i = 0;
    #pragma unroll 1
    for (; i + 4 <= cnt; i += 4) {
        int ea = s_eid[i],   ebx = s_eid[i+1];
        int ec = s_eid[i+2], edx = s_eid[i+3];
        float wa = __half2float(g_wall2[(size_t)ea *384 + wcol]);
        float wb = __half2float(g_wall2[(size_t)ebx*384 + wcol]);
        float wc = __half2float(g_wall2[(size_t)ec *384 + wcol]);
        float wd = __half2float(g_wall2[(size_t)edx*384 + wcol]);
        float sa = f0p[s_src[i  ]*32 + lane];
        float sb = f0p[s_src[i+1]*32 + lane];
        float sc = f0p[s_src[i+2]*32 + lane];
        float sd = f0p[s_src[i+3]*32 + lane];
        float wsa = wa*sa, wsb = wb*sb, wsc = wc*sc, wsd = wd*sd;
        const float* pa = &g_sh2[(size_t)(base+i  )*16 + shoff];
        const float* pb = &g_sh2[(size_t)(base+i+1)*16 + shoff];
        const float* pc = &g_sh2[(size_t)(base+i+2)*16 + shoff];
        const float* pd = &g_sh2[(size_t)(base+i+3)*16 + shoff];
        #pragma unroll
        for (int m = 0; m < dim; m++)
            acc[m] += wsa*pa[m] + wsb*pb[m] + wsc*pc[m] + wsd*pd[m];
    }
    #pragma unroll 1
    for (; i < cnt; i++) {
        int e = s_eid[i];
        float w = __half2float(g_wall2[(size_t)e*384 + wcol]);
        float s = f0p[s_src[i]*32 + lane];
        float ws = w*s;
        const float* shp = &g_sh2[(size_t)(base+i)*16 + shoff];
        #pragma unroll
        for (int m = 0; m < dim; m++) acc[m] += ws*shp[m];
    }
}

// ---------------- layer einsum (per-warp, no block barriers inside) ----------
template<int LVAL>
__device__ __forceinline__ void layer_einsum(int t, int lane, bool uself,
                                             const float* __restrict__ sw,
                                             const float* __restrict__ mw,
                                             const float* acc,
                                             const float* s_f, float* s_agg, float* s_new) {
    constexpr int dim = 2*LVAL + 1;
    constexpr int off = 32*LVAL*LVAL;
    #pragma unroll
    for (int m = 0; m < dim; m++) s_agg[off + lane*dim + m] = acc[m];
    __syncwarp();

    float o[dim];
    #pragma unroll
    for (int m = 0; m < dim; m++) o[m] = 0.f;
    const float* swp = sw + (size_t)((t*4 + LVAL)*32)*32;
    const float* mwp = mw + (size_t)((t*4 + LVAL)*32)*32;
    if (LVAL > 0 && !uself) {
        #pragma unroll 4
        for (int c = 0; c < 32; c++) {
            float wmv = mwp[c*32 + lane];
            #pragma unroll
            for (int m = 0; m < dim; m++)
                o[m] += s_agg[off + c*dim + m]*wmv;
        }
    } else {
        #pragma unroll 4
        for (int c = 0; c < 32; c++) {
            float wsv = swp[c*32 + lane];
            float wmv = mwp[c*32 + lane];
            #pragma unroll
            for (int m = 0; m < dim; m++)
                o[m] += s_f[off + c*dim + m]*wsv + s_agg[off + c*dim + m]*wmv;
        }
    }
    #pragma unroll
    for (int m = 0; m < dim; m++) s_new[off + lane*dim + m] = o[m];
}

__global__ void k_layer(int t,
                        const float* __restrict__ sw, const float* __restrict__ mw,
                        const float* __restrict__ gw,
                        float* __restrict__ outp) {
    const float* fp  = (t == 1) ? g_fb : g_fa;
    float* fn        = (t == 0) ? g_fb : ((t == 1) ? g_fa : outp);
    const float* f0p = (t == 1) ? g_f0b : g_f0a;
    float* f0n       = (t == 1) ? g_f0a : g_f0b;

    __shared__ float s_f[FD], s_agg[FD], s_new[FD], s_gate[32];
    __shared__ int s_eid[128], s_src[128];
    int n = blockIdx.x;
    int tid = threadIdx.x, l = tid >> 5, lane = tid & 31;

    if (t == 0) {
        #pragma unroll
        for (int k = 0; k < 4; k++) {
            int idx = tid + k*128;
            s_f[idx] = (idx < 32) ? g_f0a[n*32 + idx] : 0.f;
        }
    } else {
        #pragma unroll
        for (int k = 0; k < 4; k++)
            s_f[tid + k*128] = fp[(size_t)n*FD + tid + k*128];
    }

    int e0 = g_off[n], e1 = g_off[n+1];
    const int wcol = t*128 + l*32 + lane;

    float acc[7] = {0,0,0,0,0,0,0};
    // chunked cooperative edge-list prefetch; barriers are block-uniform (same e0/e1)
    #pragma unroll 1
    for (int base = e0; base < e1; base += 128) {
        int cnt = min(128, e1 - base);
        __syncthreads();
        for (int i = tid; i < cnt; i += 128) {
            s_eid[i] = g_eid[base + i];
            s_src[i] = g_src[base + i];
        }
        __syncthreads();
        switch (l) {
            case 0: gather_chunk<0>(wcol, lane, base, cnt, s_eid, s_src, f0p, acc); break;
            case 1: gather_chunk<1>(wcol, lane, base, cnt, s_eid, s_src, f0p, acc); break;
            case 2: gather_chunk<2>(wcol, lane, base, cnt, s_eid, s_src, f0p, acc); break;
            default: gather_chunk<3>(wcol, lane, base, cnt, s_eid, s_src, f0p, acc); break;
        }
    }
    __syncthreads();   // s_f ready for einsum (also orders last chunk)

    bool uself = (t != 0);
    switch (l) {
        case 0: layer_einsum<0>(t, lane, uself, sw, mw, acc, s_f, s_agg, s_new); break;
        case 1: layer_einsum<1>(t, lane, uself, sw, mw, acc, s_f, s_agg, s_new); break;
        case 2: layer_einsum<2>(t, lane, uself, sw, mw, acc, s_f, s_agg, s_new); break;
        default: layer_einsum<3>(t, lane, uself, sw, mw, acc, s_f, s_agg, s_new); break;
    }
    __syncthreads();

    if (l == 0) {
        float g = 0.f;
        #pragma unroll 4
        for (int c = 0; c < 32; c++)
            g += s_new[c] * gw[(t*32 + c)*32 + lane];
        s_gate[lane] = 1.0f / (1.0f + expf(-g));
    }
    __syncthreads();

    #pragma unroll
    for (int k = 0; k < 4; k++) {
        int idx = tid + k*128;
        float v = s_new[idx];
        float outv;
        if (idx < 32) {
            outv = v / (1.0f + expf(-v));
            f0n[n*32 + idx] = outv;
        } else {
            int d;
            if (idx < 128)      d = (idx - 32) / 3;
            else if (idx < 288) d = (idx - 128) / 5;
            else                d = (idx - 288) / 7;
            outv = v * s_gate[d];
        }
        fn[(size_t)n*FD + idx] = outv;
    }
}

// ---------------- edge output: 8 edges per 256-thread block ----------------
__global__ void k_edge_out(const int* __restrict__ ei, float* __restrict__ out) {
    __shared__ float s_g[8][32], s_sh[8][16], s_ew[8][128];
    int tid = threadIdx.x;
    int eb = blockIdx.x*8;

    #pragma unroll
    for (int q = 0; q < 4; q++) {
        int i = tid + q*256;
        int el = i >> 7, col = i & 127;
        s_ew[el][col] = __half2float(g_ew2[(size_t)(eb+el)*128 + col]);
    }
    {
        int el = tid >> 5, c = tid & 31;
        int e = eb + el;
        int sn = ei[e], dn = ei[EE + e];
        s_g[el][c] = g_f0b[sn*32 + c] + g_f0b[dn*32 + c];
    }
    if (tid < 128) {
        int el = tid >> 4, q = tid & 15;
        s_sh[el][q] = g_sh[(size_t)(eb+el)*16 + q];
    }
    __syncthreads();

    int t = tid & 127, half = tid >> 7;
    int idx0 = t*4;
    int lv[4], cv[4], mv[4];
    #pragma unroll
    for (int j = 0; j < 4; j++) {
        int idx = idx0 + j;
        if (idx < 32)       { lv[j] = 0; cv[j] = idx;      mv[j] = 0; }
        else if (idx < 128) { int r = idx - 32;  lv[j] = 1; cv[j] = r/3; mv[j] = r - 3*cv[j]; }
        else if (idx < 288) { int r = idx - 128; lv[j] = 2; cv[j] = r/5; mv[j] = r - 5*cv[j]; }
        else                { int r = idx - 288; lv[j] = 3; cv[j] = r/7; mv[j] = r - 7*cv[j]; }
    }
    #pragma unroll
    for (int p = 0; p < 4; p++) {
        int el = p*2 + half;
        float4 v;
        float* pv = &v.x;
        #pragma unroll
        for (int j = 0; j < 4; j++)
            pv[j] = s_ew[el][lv[j]*32 + cv[j]] * s_g[el][cv[j]] * s_sh[el][lv[j]*lv[j] + mv[j]];
        *(float4*)&out[(size_t)(NN + eb + el)*FD + idx0] = v;
    }
}

// ---------------- launch ----------------
extern "C" void kernel_launch(void* const* d_in, const int* in_sizes, int n_in,
                              void* d_out, int out_size) {
    const float* pos        = (const float*)d_in[0];
    const float* node_embed = (const float*)d_in[1];
    const float* rw1        = (const float*)d_in[2];
    const float* rb1        = (const float*)d_in[3];
    const float* rw2        = (const float*)d_in[4];
    const float* rb2        = (const float*)d_in[5];
    const float* self_w     = (const float*)d_in[6];
    const float* msg_w      = (const float*)d_in[7];
    const float* gate_w     = (const float*)d_in[8];
    const float* edge_w     = (const float*)d_in[9];
    const float* edge_b     = (const float*)d_in[10];
    const int*   species    = (const int*)d_in[11];
    const int*   ei         = (const int*)d_in[12];
    float* out = (float*)d_out;

    cudaFuncSetAttribute(k_geomh, cudaFuncAttributeMaxDynamicSharedMemorySize, GEOMH_SMEM);
    cudaFuncSetAttribute(k_gemm, cudaFuncAttributeMaxDynamicSharedMemorySize, GEMM_SMEM);

    // slot 0,1: CSR front
    k_zero<<<(NN+255)/256, 256>>>();
    k_hist<<<(EE+255)/256, 256>>>(ei);

    // slot 2: fused geometry + radial + MLP1 (packed output)
    k_geomh<<<EE/128, 256, GEOMH_SMEM>>>(pos, rw1, rb1, ei);

    // slot 3 (profiled): GEMM2 -> g_wall2 + g_ew2 (edge order, fp16)
    dim3 gg(EE/128, 4);
    k_gemm<<<gg, 256, GEMM_SMEM>>>(rw2, edge_w, rb2, edge_b);

    // slot 4,5: CSR scan + fill (eid/src/sh2)
    k_scan<<<1, 1024>>>();
    k_fill<<<(EE+255)/256, 256>>>(ei);

    // compact node features
    k_init<<<(NN*CC + 255)/256, 256>>>(node_embed, species);

    // 3 message-passing layers; last writes node rows of d_out directly
    for (int t = 0; t < 3; t++)
        k_layer<<<NN, 128>>>(t, self_w, msg_w, gate_w, out);

    // edge rows of d_out
    k_edge_out<<<EE/8, 256>>>(ei, out);
}

// round 16
// speedup vs baseline: 1.6981x; 1.0224x over previous
#include <cuda_runtime.h>
#include <cuda_fp16.h>
#include <math.h>
#include <cstdint>

#define NN 10000
#define EE 160000
#define CC 32
#define NB 128
#define HH 64
#define FD 512   // C * (1+3+5+7)

typedef unsigned long long u64t;
typedef ulonglong2 u642;

// ---------------- scratch (device globals; no allocation) ----------------
__device__ u64t   g_hp[(size_t)EE*32];     // 41 MB  : hidden, packed m-pair layout [b][k][mp]
__device__ float  g_sh[(size_t)EE*16];     // 10 MB  : sph harmonics, edge order
__device__ float  g_sh2[(size_t)EE*16];    // 10 MB  : sph harmonics, CSR order
__device__ __half g_wall2[(size_t)EE*384]; // 123 MB : layer weights, edge order, fp16
__device__ __half g_ew2[(size_t)EE*128];   // 41 MB  : edge-out weights, edge order, fp16
__device__ float  g_fa[(size_t)NN*FD];     // 20 MB  : node features buf A
__device__ float  g_fb[(size_t)NN*FD];     // 20 MB  : node features buf B
__device__ float  g_f0a[(size_t)NN*CC];    // 1.28 MB: compact f0 buf A
__device__ float  g_f0b[(size_t)NN*CC];    // 1.28 MB: compact f0 buf B
__device__ int    g_cnt[NN];
__device__ int    g_cnt2[NN];
__device__ int    g_off[NN+1];
__device__ int    g_eid[EE];               // CSR position -> edge
__device__ int    g_src[EE];               // CSR position -> src node

// ---------------- packed fp32 helpers ----------------
__device__ __forceinline__ u64t pack2(float v) {
    u64t r; asm("mov.b64 %0, {%1, %1};" : "=l"(r) : "f"(v)); return r;
}
__device__ __forceinline__ u64t pack2two(float lo, float hi) {
    u64t r; asm("mov.b64 %0, {%1, %2};" : "=l"(r) : "f"(lo), "f"(hi)); return r;
}
__device__ __forceinline__ void unpack2(u64t v, float& lo, float& hi) {
    asm("mov.b64 {%0, %1}, %2;" : "=f"(lo), "=f"(hi) : "l"(v));
}
__device__ __forceinline__ void ffma2(u64t& d, u64t a, u64t b) {
    asm("fma.rn.f32x2 %0, %1, %2, %0;" : "+l"(d) : "l"(a), "l"(b));
}

// ---------------- CSR build ----------------
__global__ void k_zero() {
    int i = blockIdx.x*blockDim.x + threadIdx.x;
    if (i < NN) { g_cnt[i] = 0; g_cnt2[i] = 0; }
}

__global__ void k_hist(const int* __restrict__ ei) {
    int e = blockIdx.x*blockDim.x + threadIdx.x;
    if (e < EE) atomicAdd(&g_cnt[ei[EE + e]], 1);
}

// one-pass parallel scan: 1024 threads, 10 contiguous elems each (NN = 1000*10)
__global__ void k_scan() {
    __shared__ int wsum[32];
    int t = threadIdx.x;
    int lane = t & 31, wid = t >> 5;
    int base = t*10;
    int loc[10];
    int s = 0;
    if (t < 1000) {
        #pragma unroll
        for (int j = 0; j < 10; j++) { s += g_cnt[base + j]; loc[j] = s; }
    }
    int v = s;
    #pragma unroll
    for (int o = 1; o < 32; o <<= 1) {
        int u = __shfl_up_sync(0xFFFFFFFF, v, o);
        if (lane >= o) v += u;
    }
    if (lane == 31) wsum[wid] = v;
    __syncthreads();
    if (wid == 0) {
        int w = wsum[lane];
        #pragma unroll
        for (int o = 1; o < 32; o <<= 1) {
            int u = __shfl_up_sync(0xFFFFFFFF, w, o);
            if (lane >= o) w += u;
        }
        wsum[lane] = w;
    }
    __syncthreads();
    int excl = v - s + (wid > 0 ? wsum[wid-1] : 0);
    if (t < 1000) {
        #pragma unroll
        for (int j = 0; j < 10; j++) g_off[base + j + 1] = excl + loc[j];
    }
    if (t == 0) g_off[0] = 0;
}

// fill: eid/src permutation + CSR-ordered copy of sh
__global__ void k_fill(const int* __restrict__ ei) {
    int e = blockIdx.x*blockDim.x + threadIdx.x;
    if (e < EE) {
        int d = ei[EE + e];
        int p = atomicAdd(&g_cnt2[d], 1);
        int slot = g_off[d] + p;
        g_eid[slot] = e;
        g_src[slot] = ei[e];
        const float4* src = (const float4*)&g_sh[(size_t)e*16];
        float4* dst = (float4*)&g_sh2[(size_t)slot*16];
        dst[0] = src[0]; dst[1] = src[1]; dst[2] = src[2]; dst[3] = src[3];
    }
}

// ---------------- fused: geometry + sh + radial basis + MLP1 (f32x2, 128 edges/block) ----
// radial basis via Chebyshev recurrence (3 MUFU seeds instead of 64 MUFU per thread)
#define GEOMH_SMEM 99328
__global__ void k_geomh(const float* __restrict__ pos, const float* __restrict__ rw1,
                        const float* __restrict__ rb1, const int* __restrict__ ei) {
    extern __shared__ char smem[];
    float* rb_s = (float*)smem;
    float* b1_s = (float*)(smem + 65536);
    float* su   = (float*)(smem + 98304);
    float* ss   = (float*)(smem + 98816);
    int tid = threadIdx.x;
    int eb = blockIdx.x*128;

    if (tid < 128) {
        int e = eb + tid;
        int sn = ei[e], dn = ei[EE + e];
        float vx = pos[dn*3+0] - pos[sn*3+0];
        float vy = pos[dn*3+1] - pos[sn*3+1];
        float vz = pos[dn*3+2] - pos[sn*3+2];
        float r2 = vx*vx + vy*vy + vz*vz + 1e-12f;
        float r  = sqrtf(r2);
        float inv_r = 1.0f / r;
        float x = vx*inv_r, y = vy*inv_r, z = vz*inv_r;

        const float s3  = 1.7320508075688772f;
        const float s15 = 3.872983346207417f;
        const float s5h = 1.118033988749895f;
        const float s15h= 1.9364916731037085f;
        const float c1  = 2.091650066335189f;
        const float c2  = 10.246950765959598f;
        const float c3  = 1.6201851746019651f;
        const float c4  = 1.3228756555322954f;
        const float c5  = 5.123475382979799f;
        float4 q0 = make_float4(1.0f, s3*x, s3*y, s3*z);
        float4 q1 = make_float4(s15*x*y, s15*y*z, s5h*(3.0f*z*z - 1.0f), s15*x*z);
        float4 q2 = make_float4(s15h*(x*x - y*y), c1*y*(3.0f*x*x - y*y), c2*x*y*z,
                                c3*y*(5.0f*z*z - 1.0f));
        float4 q3 = make_float4(c4*(5.0f*z*z*z - 3.0f*z), c3*x*(5.0f*z*z - 1.0f),
                                c5*z*(x*x - y*y), c1*x*(x*x - 3.0f*y*y));
        float4* shp = (float4*)&g_sh[(size_t)e*16];
        shp[0] = q0; shp[1] = q1; shp[2] = q2; shp[3] = q3;

        float u = fminf(r * 0.2f, 1.0f);
        float env = 0.5f * (cospif(u) + 1.0f);
        su[tid] = u;
        ss[tid] = env * 0.6324555320336759f * inv_r;
    }
    {
        const float4* src = (const float4*)rw1;
        float4* dst = (float4*)b1_s;
        #pragma unroll
        for (int i = tid; i < 2048; i += 256) dst[i] = src[i];
    }
    __syncthreads();

    // phase B: radial basis via sin recurrence
    // rb[k] = sc * sin(pi (k+1) u);  sin(pi(n+1)u) = 2cos(pi u) sin(pi n u) - sin(pi(n-1)u)
    {
        int e = tid & 127, kh = tid >> 7;
        float u = su[e], sc = ss[e];
        float c = 2.0f * cospif(u);
        float p0, p1;
        if (kh == 0) { p0 = 0.0f;              p1 = sinpif(u); }          // n=0, n=1
        else         { p0 = sinpif(64.0f*u);   p1 = sinpif(65.0f*u); }    // n=64, n=65
        int kbase = kh*64;
        #pragma unroll 4
        for (int j = 0; j < 64; j++) {
            rb_s[(kbase + j)*128 + e] = sc * p1;          // k = kbase+j -> n = k+1
            float nx2 = __fmaf_rn(c, p1, -p0);
            p0 = p1; p1 = nx2;
        }
    }
    __syncthreads();

    int ty = tid >> 4, tx = tid & 15;
    u64t acc[4][4];
    #pragma unroll
    for (int p = 0; p < 4; p++)
        #pragma unroll
        for (int c = 0; c < 4; c++) acc[p][c] = 0ull;

    #pragma unroll 4
    for (int k = 0; k < 128; k++) {
        u64t ap[4];
        #pragma unroll
        for (int p = 0; p < 4; p++)
            ap[p] = *(const u64t*)&rb_s[k*128 + ty*8 + 2*p];
        float4 bv = *(const float4*)&b1_s[k*64 + tx*4];
        u64t bp[4] = {pack2(bv.x), pack2(bv.y), pack2(bv.z), pack2(bv.w)};
        #pragma unroll
        for (int p = 0; p < 4; p++)
            #pragma unroll
            for (int c = 0; c < 4; c++)
                ffma2(acc[p][c], ap[p], bp[c]);
    }

    // silu + bias, keep in registers
    float4 bias = *(const float4*)&rb1[tx*4];
    float bb[4] = {bias.x, bias.y, bias.z, bias.w};
    float lov[4][4], hiv[4][4];
    #pragma unroll
    for (int p = 0; p < 4; p++) {
        #pragma unroll
        for (int c = 0; c < 4; c++) {
            float lo, hi;
            unpack2(acc[p][c], lo, hi);
            float a = lo + bb[c];
            float b = hi + bb[c];
            lov[p][c] = a / (1.0f + expf(-a));
            hiv[p][c] = b / (1.0f + expf(-b));
        }
    }

    // transpose bounce through smem (rb_s dead) into packed m-pair layout, stride 66
    __syncthreads();
    {
        u64t* pk = (u64t*)smem;
        #pragma unroll
        for (int p = 0; p < 4; p++) {
            int mp = ty*4 + p;
            #pragma unroll
            for (int c = 0; c < 4; c++) {
                int k = tx*4 + c;
                pk[k*66 + mp] = pack2two(lov[p][c], hiv[p][c]);
            }
        }
    }
    __syncthreads();
    {
        const u64t* pk = (const u64t*)smem;
        u642* dst = (u642*)&g_hp[(size_t)blockIdx.x*4096];
        #pragma unroll
        for (int q = 0; q < 8; q++) {
            int li = tid + q*256;
            int k = li >> 5, mq = li & 31;
            dst[li] = *(const u642*)&pk[k*66 + mq*2];
        }
    }
}

// ---------------- GEMM2 (f32x2, fp16 out; zero-transpose A staging; LDS.128 A) ----
#define AST 66
#define BST 132
#define GEMM_SMEM (64*AST*8 + 64*BST*4)   // 33792 + 33792 = 67584
__global__ void k_gemm(const float* __restrict__ rw2, const float* __restrict__ edge_w,
                       const float* __restrict__ rb2, const float* __restrict__ edge_b) {
    extern __shared__ char smg[];
    u64t*  As2 = (u64t*)smg;
    float* Bs  = (float*)(smg + 64*AST*8);
    int tid = threadIdx.x;
    int bx = blockIdx.x, by = blockIdx.y;
    int eb = bx*128;

    // stage A: pure coalesced copy, no transpose
    {
        const u642* src = (const u642*)&g_hp[(size_t)bx*4096];
        #pragma unroll
        for (int q = 0; q < 8; q++) {
            int li = tid + q*256;
            int k = li >> 5, mq = li & 31;
            *(u642*)&As2[k*AST + mq*2] = src[li];
        }
    }
    #pragma unroll
    for (int p = 0; p < 8; p++) {
        int li = tid + p*256;
        int k = li >> 5, n4 = li & 31;
        int jg = by*128 + n4*4;
        float4 v = (jg < 384) ? *(const float4*)&rw2[k*384 + jg]
                              : *(const float4*)&edge_w[k*128 + (jg - 384)];
        *(float4*)&Bs[k*BST + n4*4] = v;
    }
    __syncthreads();

    int my = tid >> 4, nx = tid & 15;
    u64t acc[4][8];
    #pragma unroll
    for (int i = 0; i < 4; i++)
        #pragma unroll
        for (int n = 0; n < 8; n++) acc[i][n] = 0ull;

    #pragma unroll 8
    for (int k = 0; k < 64; k++) {
        u642 A0 = *(const u642*)&As2[k*AST + my*4];
        u642 A1 = *(const u642*)&As2[k*AST + my*4 + 2];
        u64t a[4] = {A0.x, A0.y, A1.x, A1.y};
        float4 b0 = *(const float4*)&Bs[k*BST + nx*8];
        float4 b1 = *(const float4*)&Bs[k*BST + nx*8 + 4];
        u64t bp[8] = {pack2(b0.x), pack2(b0.y), pack2(b0.z), pack2(b0.w),
                      pack2(b1.x), pack2(b1.y), pack2(b1.z), pack2(b1.w)};
        #pragma unroll
        for (int i = 0; i < 4; i++)
            #pragma unroll
            for (int n = 0; n < 8; n++)
                ffma2(acc[i][n], a[i], bp[n]);
    }

    float bj[8];
    #pragma unroll
    for (int n = 0; n < 8; n++) {
        int jg = by*128 + nx*8 + n;
        bj[n] = (jg < 384) ? rb2[jg] : edge_b[jg - 384];
    }

    #pragma unroll
    for (int i = 0; i < 4; i++) {
        float lo[8], hi[8];
        #pragma unroll
        for (int n = 0; n < 8; n++) {
            unpack2(acc[i][n], lo[n], hi[n]);
            lo[n] += bj[n]; hi[n] += bj[n];
        }
        int er0 = eb + my*8 + 2*i;
        __half* dst;
        size_t r0, r1;
        if (by < 3) {
            dst = g_wall2;
            r0 = (size_t)er0*384       + by*128 + nx*8;
            r1 = (size_t)(er0 + 1)*384 + by*128 + nx*8;
        } else {
            dst = g_ew2;
            r0 = (size_t)er0*128       + nx*8;
            r1 = (size_t)(er0 + 1)*128 + nx*8;
        }
        __half2 a0 = __floats2half2_rn(lo[0], lo[1]);
        __half2 a1 = __floats2half2_rn(lo[2], lo[3]);
        __half2 a2 = __floats2half2_rn(lo[4], lo[5]);
        __half2 a3 = __floats2half2_rn(lo[6], lo[7]);
        uint4 u0;
        u0.x = *(unsigned*)&a0; u0.y = *(unsigned*)&a1;
        u0.z = *(unsigned*)&a2; u0.w = *(unsigned*)&a3;
        *(uint4*)&dst[r0] = u0;
        __half2 c0 = __floats2half2_rn(hi[0], hi[1]);
        __half2 c1 = __floats2half2_rn(hi[2], hi[3]);
        __half2 c2 = __floats2half2_rn(hi[4], hi[5]);
        __half2 c3 = __floats2half2_rn(hi[6], hi[7]);
        uint4 u1;
        u1.x = *(unsigned*)&c0; u1.y = *(unsigned*)&c1;
        u1.z = *(unsigned*)&c2; u1.w = *(unsigned*)&c3;
        *(uint4*)&dst[r1] = u1;
    }
}

// ---------------- node feature init (compact f0 only) ----------------
__global__ void k_init(const float* __restrict__ node_embed, const int* __restrict__ species) {
    int i = blockIdx.x*blockDim.x + threadIdx.x;
    if (i < NN*CC) {
        int n = i >> 5, idx = i & 31;
        g_f0a[i] = node_embed[species[n]*32 + idx];
    }
}

// ---------------- layer gather over one prefetched chunk (no block barriers inside) ----
template<int LVAL>
__device__ __forceinline__ void gather_chunk(int wcol, int lane, int base, int cnt,
                                             const int* s_eid, const int* s_src,
                                             const float* __restrict__ f0p, float* acc) {
    constexpr int dim = 2*LVAL + 1;
    constexpr int shoff = LVAL*LVAL;
    int i = 0;
    #pragma unroll 1
    for (; i + 4 <= cnt; i += 4) {
        int ea = s_eid[i],   ebx = s_eid[i+1];
        int ec = s_eid[i+2], edx = s_eid[i+3];
        float wa = __half2float(g_wall2[(size_t)ea *384 + wcol]);
        float wb = __half2float(g_wall2[(size_t)ebx*384 + wcol]);
        float wc = __half2float(g_wall2[(size_t)ec *384 + wcol]);
        float wd = __half2float(g_wall2[(size_t)edx*384 + wcol]);
        float sa = f0p[s_src[i  ]*32 + lane];
        float sb = f0p[s_src[i+1]*32 + lane];
        float sc = f0p[s_src[i+2]*32 + lane];
        float sd = f0p[s_src[i+3]*32 + lane];
        float wsa = wa*sa, wsb = wb*sb, wsc = wc*sc, wsd = wd*sd;
        const float* pa = &g_sh2[(size_t)(base+i  )*16 + shoff];
        const float* pb = &g_sh2[(size_t)(base+i+1)*16 + shoff];
        const float* pc = &g_sh2[(size_t)(base+i+2)*16 + shoff];
        const float* pd = &g_sh2[(size_t)(base+i+3)*16 + shoff];
        #pragma unroll
        for (int m = 0; m < dim; m++)
            acc[m] += wsa*pa[m] + wsb*pb[m] + wsc*pc[m] + wsd*pd[m];
    }
    #pragma unroll 1
    for (; i < cnt; i++) {
        int e = s_eid[i];
        float w = __half2float(g_wall2[(size_t)e*384 + wcol]);
        float s = f0p[s_src[i]*32 + lane];
        float ws = w*s;
        const float* shp = &g_sh2[(size_t)(base+i)*16 + shoff];
        #pragma unroll
        for (int m = 0; m < dim; m++) acc[m] += ws*shp[m];
    }
}

// ---------------- layer einsum (per-warp, no block barriers inside) ----------
template<int LVAL>
__device__ __forceinline__ void layer_einsum(int t, int lane, bool uself,
                                             const float* __restrict__ sw,
                                             const float* __restrict__ mw,
                                             const float* acc,
                                             const float* s_f, float* s_agg, float* s_new) {
    constexpr int dim = 2*LVAL + 1;
    constexpr int off = 32*LVAL*LVAL;
    #pragma unroll
    for (int m = 0; m < dim; m++) s_agg[off + lane*dim + m] = acc[m];
    __syncwarp();

    float o[dim];
    #pragma unroll
    for (int m = 0; m < dim; m++) o[m] = 0.f;
    const float* swp = sw + (size_t)((t*4 + LVAL)*32)*32;
    const float* mwp = mw + (size_t)((t*4 + LVAL)*32)*32;
    if (LVAL > 0 && !uself) {
        #pragma unroll 4
        for (int c = 0; c < 32; c++) {
            float wmv = mwp[c*32 + lane];
            #pragma unroll
            for (int m = 0; m < dim; m++)
                o[m] += s_agg[off + c*dim + m]*wmv;
        }
    } else {
        #pragma unroll 4
        for (int c = 0; c < 32; c++) {
            float wsv = swp[c*32 + lane];
            float wmv = mwp[c*32 + lane];
            #pragma unroll
            for (int m = 0; m < dim; m++)
                o[m] += s_f[off + c*dim + m]*wsv + s_agg[off + c*dim + m]*wmv;
        }
    }
    #pragma unroll
    for (int m = 0; m < dim; m++) s_new[off + lane*dim + m] = o[m];
}

__global__ void k_layer(int t,
                        const float* __restrict__ sw, const float* __restrict__ mw,
                        const float* __restrict__ gw,
                        float* __restrict__ outp) {
    const float* fp  = (t == 1) ? g_fb : g_fa;
    float* fn        = (t == 0) ? g_fb : ((t == 1) ? g_fa : outp);
    const float* f0p = (t == 1) ? g_f0b : g_f0a;
    float* f0n       = (t == 1) ? g_f0a : g_f0b;

    __shared__ float s_f[FD], s_agg[FD], s_new[FD], s_gate[32];
    __shared__ int s_eid[128], s_src[128];
    int n = blockIdx.x;
    int tid = threadIdx.x, l = tid >> 5, lane = tid & 31;

    if (t == 0) {
        #pragma unroll
        for (int k = 0; k < 4; k++) {
            int idx = tid + k*128;
            s_f[idx] = (idx < 32) ? g_f0a[n*32 + idx] : 0.f;
        }
    } else {
        #pragma unroll
        for (int k = 0; k < 4; k++)
            s_f[tid + k*128] = fp[(size_t)n*FD + tid + k*128];
    }

    int e0 = g_off[n], e1 = g_off[n+1];
    const int wcol = t*128 + l*32 + lane;

    float acc[7] = {0,0,0,0,0,0,0};
    #pragma unroll 1
    for (int base = e0; base < e1; base += 128) {
        int cnt = min(128, e1 - base);
        __syncthreads();
        for (int i = tid; i < cnt; i += 128) {
            s_eid[i] = g_eid[base + i];
            s_src[i] = g_src[base + i];
        }
        __syncthreads();
        switch (l) {
            case 0: gather_chunk<0>(wcol, lane, base, cnt, s_eid, s_src, f0p, acc); break;
            case 1: gather_chunk<1>(wcol, lane, base, cnt, s_eid, s_src, f0p, acc); break;
            case 2: gather_chunk<2>(wcol, lane, base, cnt, s_eid, s_src, f0p, acc); break;
            default: gather_chunk<3>(wcol, lane, base, cnt, s_eid, s_src, f0p, acc); break;
        }
    }
    __syncthreads();

    bool uself = (t != 0);
    switch (l) {
        case 0: layer_einsum<0>(t, lane, uself, sw, mw, acc, s_f, s_agg, s_new); break;
        case 1: layer_einsum<1>(t, lane, uself, sw, mw, acc, s_f, s_agg, s_new); break;
        case 2: layer_einsum<2>(t, lane, uself, sw, mw, acc, s_f, s_agg, s_new); break;
        default: layer_einsum<3>(t, lane, uself, sw, mw, acc, s_f, s_agg, s_new); break;
    }
    __syncthreads();

    if (l == 0) {
        float g = 0.f;
        #pragma unroll 4
        for (int c = 0; c < 32; c++)
            g += s_new[c] * gw[(t*32 + c)*32 + lane];
        s_gate[lane] = 1.0f / (1.0f + expf(-g));
    }
    __syncthreads();

    #pragma unroll
    for (int k = 0; k < 4; k++) {
        int idx = tid + k*128;
        float v = s_new[idx];
        float outv;
        if (idx < 32) {
            outv = v / (1.0f + expf(-v));
            f0n[n*32 + idx] = outv;
        } else {
            int d;
            if (idx < 128)      d = (idx - 32) / 3;
            else if (idx < 288) d = (idx - 128) / 5;
            else                d = (idx - 288) / 7;
            outv = v * s_gate[d];
        }
        fn[(size_t)n*FD + idx] = outv;
    }
}

// ---------------- edge output: 8 edges per 256-thread block ----------------
__global__ void k_edge_out(const int* __restrict__ ei, float* __restrict__ out) {
    __shared__ float s_g[8][32], s_sh[8][16], s_ew[8][128];
    int tid = threadIdx.x;
    int eb = blockIdx.x*8;

    #pragma unroll
    for (int q = 0; q < 4; q++) {
        int i = tid + q*256;
        int el = i >> 7, col = i & 127;
        s_ew[el][col] = __half2float(g_ew2[(size_t)(eb+el)*128 + col]);
    }
    {
        int el = tid >> 5, c = tid & 31;
        int e = eb + el;
        int sn = ei[e], dn = ei[EE + e];
        s_g[el][c] = g_f0b[sn*32 + c] + g_f0b[dn*32 + c];
    }
    if (tid < 128) {
        int el = tid >> 4, q = tid & 15;
        s_sh[el][q] = g_sh[(size_t)(eb+el)*16 + q];
    }
    __syncthreads();

    int t = tid & 127, half = tid >> 7;
    int idx0 = t*4;
    int lv[4], cv[4], mv[4];
    #pragma unroll
    for (int j = 0; j < 4; j++) {
        int idx = idx0 + j;
        if (idx < 32)       { lv[j] = 0; cv[j] = idx;      mv[j] = 0; }
        else if (idx < 128) { int r = idx - 32;  lv[j] = 1; cv[j] = r/3; mv[j] = r - 3*cv[j]; }
        else if (idx < 288) { int r = idx - 128; lv[j] = 2; cv[j] = r/5; mv[j] = r - 5*cv[j]; }
        else                { int r = idx - 288; lv[j] = 3; cv[j] = r/7; mv[j] = r - 7*cv[j]; }
    }
    #pragma unroll
    for (int p = 0; p < 4; p++) {
        int el = p*2 + half;
        float4 v;
        float* pv = &v.x;
        #pragma unroll
        for (int j = 0; j < 4; j++)
            pv[j] = s_ew[el][lv[j]*32 + cv[j]] * s_g[el][cv[j]] * s_sh[el][lv[j]*lv[j] + mv[j]];
        *(float4*)&out[(size_t)(NN + eb + el)*FD + idx0] = v;
    }
}

// ---------------- launch ----------------
extern "C" void kernel_launch(void* const* d_in, const int* in_sizes, int n_in,
                              void* d_out, int out_size) {
    const float* pos        = (const float*)d_in[0];
    const float* node_embed = (const float*)d_in[1];
    const float* rw1        = (const float*)d_in[2];
    const float* rb1        = (const float*)d_in[3];
    const float* rw2        = (const float*)d_in[4];
    const float* rb2        = (const float*)d_in[5];
    const float* self_w     = (const float*)d_in[6];
    const float* msg_w      = (const float*)d_in[7];
    const float* gate_w     = (const float*)d_in[8];
    const float* edge_w     = (const float*)d_in[9];
    const float* edge_b     = (const float*)d_in[10];
    const int*   species    = (const int*)d_in[11];
    const int*   ei         = (const int*)d_in[12];
    float* out = (float*)d_out;

    cudaFuncSetAttribute(k_geomh, cudaFuncAttributeMaxDynamicSharedMemorySize, GEOMH_SMEM);
    cudaFuncSetAttribute(k_gemm, cudaFuncAttributeMaxDynamicSharedMemorySize, GEMM_SMEM);

    // slot 0,1,2: CSR front
    k_zero<<<(NN+255)/256, 256>>>();
    k_hist<<<(EE+255)/256, 256>>>(ei);
    k_scan<<<1, 1024>>>();

    // slot 3 (profiled): fused geometry + radial + MLP1
    k_geomh<<<EE/128, 256, GEOMH_SMEM>>>(pos, rw1, rb1, ei);

    // GEMM2 -> g_wall2 + g_ew2 (edge order, fp16)
    dim3 gg(EE/128, 4);
    k_gemm<<<gg, 256, GEMM_SMEM>>>(rw2, edge_w, rb2, edge_b);

    // CSR fill (eid/src/sh2)
    k_fill<<<(EE+255)/256, 256>>>(ei);

    // compact node features
    k_init<<<(NN*CC + 255)/256, 256>>>(node_embed, species);

    // 3 message-passing layers; last writes node rows of d_out directly
    for (int t = 0; t < 3; t++)
        k_layer<<<NN, 128>>>(t, self_w, msg_w, gate_w, out);

    // edge rows of d_out
    k_edge_out<<<EE/8, 256>>>(ei, out);
}